// round 11
// baseline (speedup 1.0000x reference)
#include <cuda_runtime.h>
#include <math.h>
#include <stdint.h>

#define NQ    1024
#define FEWS  5
#define MCAND 200
#define KSEL  32
#define DD    128
#define DMM   256
#define DFF   512
#define HHH   512
#define GC    1024            // compacted gate columns, interleaved (j*4 + gate)
#define RTOT  (NQ + FEWS)     // 1029
#define NBLK  (2*NQ + 2*FEWS) // 2058 neighbor tasks

// ---------------- workspace (device globals; no allocations) ----------------
__device__ float g_mcat [NBLK * DMM];       // per-task K-mean [rel;ent]
__device__ float g_cat  [RTOT * DMM];
__device__ float g_h1   [RTOT * DFF];
__device__ float g_h2   [2 * RTOT * DMM];   // 2 split-K planes
__device__ float g_qg   [NQ   * DMM];
__device__ float g_sse  [FEWS * DMM];
__device__ float g_sgn  [DMM];
__device__ float g_WihC [GC * DMM];
__device__ float g_WhhC [GC * DMM];
__device__ float g_bsumC[GC];
__device__ float g_svec [GC];
__device__ float g_GxC  [NQ * GC];
__device__ float g_gates[NQ * GC];
__device__ float g_c0   [NQ * DMM];
__device__ float g_hr   [NQ * DMM];

// interleaved gate col r -> original 4H row: gate = r&3, j = r>>2, o = gate*512 + j
__device__ __forceinline__ int orig_col(int r) { return (r & 3) * 512 + (r >> 2); }

__device__ __forceinline__ float sigf(float x) { return 1.f / (1.f + expf(-x)); }

__device__ __forceinline__ uint32_t f2tf(float x) {
    uint32_t r;
    asm("cvt.rna.tf32.f32 %0, %1;" : "=r"(r) : "f"(x));
    return r;
}

__device__ __forceinline__ void mma8(float* c, const uint4& a, const uint2& b) {
    asm volatile(
        "mma.sync.aligned.m16n8k8.row.col.f32.tf32.tf32.f32 "
        "{%0,%1,%2,%3}, {%4,%5,%6,%7}, {%8,%9}, {%0,%1,%2,%3};"
        : "+f"(c[0]), "+f"(c[1]), "+f"(c[2]), "+f"(c[3])
        : "r"(a.x), "r"(a.y), "r"(a.z), "r"(a.w), "r"(b.x), "r"(b.y));
}

// ---------------- weight compaction: live gate columns, interleaved ----------------
__global__ __launch_bounds__(256)
void compact_kernel(const float* __restrict__ Wih, const float* __restrict__ Whh,
                    const float* __restrict__ bih, const float* __restrict__ bhh)
{
    const int idx = blockIdx.x * 256 + threadIdx.x;   // GC*DMM threads
    const int r = idx >> 8, c = idx & 255;
    const int o = orig_col(r);
    g_WihC[idx] = Wih[(size_t)o * DMM + c];
    g_WhhC[idx] = Whh[(size_t)o * HHH + c];
    if (c == 0) g_bsumC[r] = bih[o] + bhh[o];
}

// ---------------- svec + support mean + sgn (merged) ----------------
__global__ __launch_bounds__(256)
void svec_kernel(const float* __restrict__ Whh)
{
    const int t = threadIdx.x;
    const int lane = t & 31, w = t >> 5;
    __shared__ float ssg[DMM];
    __shared__ float s1[8];
    __shared__ float s_n;

    float s = 0.f;
    #pragma unroll
    for (int r = 0; r < FEWS; r++) s += g_sse[r * DMM + t];
    ssg[t] = s * (1.f / FEWS);
    __syncthreads();

    const int r = blockIdx.x * 8 + w;      // grid 128 -> 1024 warps
    const int o = orig_col(r);
    const float* wr = Whh + (size_t)o * HHH + DMM;
    float p = 0.f;
    #pragma unroll
    for (int c = lane; c < DMM; c += 32) p += wr[c] * ssg[c];
    #pragma unroll
    for (int off = 16; off; off >>= 1) p += __shfl_down_sync(0xffffffffu, p, off);
    if (lane == 0) g_svec[r] = p;

    if (blockIdx.x == 0) {
        __syncthreads();
        float q = ssg[t] * ssg[t];
        #pragma unroll
        for (int off = 16; off; off >>= 1) q += __shfl_down_sync(0xffffffffu, q, off);
        if (lane == 0) s1[w] = q;
        __syncthreads();
        if (t == 0) {
            float S = 0.f;
            #pragma unroll
            for (int i = 0; i < 8; i++) S += s1[i];
            s_n = fmaxf(sqrtf(S), 1e-12f);
        }
        __syncthreads();
        g_sgn[t] = ssg[t] / s_n;
    }
}

// ---------------- neighbor encoder: sims + top-K + mean only ----------------
__global__ __launch_bounds__(256)
void neighbor_all(const float* __restrict__ emb,
                  const int* __restrict__ qlc, const int* __restrict__ qrc,
                  const int* __restrict__ slc, const int* __restrict__ src,
                  const int* __restrict__ query, const int* __restrict__ support)
{
    const int b = blockIdx.x;
    const int t = threadIdx.x;
    const int lane = t & 31;
    const int w = t >> 5;

    const int* conn_row;
    int cid, tt;
    if (b < NQ)            { conn_row = qlc + (size_t)b * MCAND * 2;                 cid = query[b * 2 + 0];   tt = b; }
    else if (b < 2 * NQ)   { int rb = b - NQ;        conn_row = qrc + (size_t)rb * MCAND * 2; cid = query[rb * 2 + 1];   tt = RTOT + rb; }
    else if (b < 2*NQ+FEWS){ int rb = b - 2*NQ;      conn_row = slc + (size_t)rb * MCAND * 2; cid = support[rb*2 + 0];   tt = NQ + rb; }
    else                   { int rb = b - 2*NQ-FEWS; conn_row = src + (size_t)rb * MCAND * 2; cid = support[rb*2 + 1];   tt = RTOT + NQ + rb; }

    __shared__ __align__(16) float s_center[DD];
    __shared__ float s_sim [MCAND];
    __shared__ int   s_ridx[MCAND];
    __shared__ int   s_eidx[MCAND];
    __shared__ int   s_selr[KSEL];
    __shared__ int   s_sele[KSEL];
    __shared__ float s_red[8];
    __shared__ float s_cn;

    for (int n = t; n < MCAND; n += 256) {
        s_ridx[n] = conn_row[n * 2 + 0];
        s_eidx[n] = conn_row[n * 2 + 1];
    }
    float cv = 0.f;
    if (t < DD) { cv = emb[(size_t)cid * DD + t]; s_center[t] = cv; }

    float p = cv * cv;
    #pragma unroll
    for (int o = 16; o; o >>= 1) p += __shfl_down_sync(0xffffffffu, p, o);
    if (lane == 0) s_red[w] = p;
    __syncthreads();
    if (t == 0) {
        float s = 0.f;
        #pragma unroll
        for (int i = 0; i < 8; i++) s += s_red[i];
        s_cn = sqrtf(s);
    }
    __syncthreads();
    const float cn = s_cn;

    const float4 c4 = *(const float4*)(s_center + lane * 4);
    for (int n = w; n < MCAND; n += 16) {
        const int n1 = n + 8;
        const bool h1 = n1 < MCAND;
        const float4 e0 = *(const float4*)(emb + (size_t)s_eidx[n] * DD + lane * 4);
        float4 e1 = e0;
        if (h1) e1 = *(const float4*)(emb + (size_t)s_eidx[n1] * DD + lane * 4);
        float num0 = e0.x*c4.x + e0.y*c4.y + e0.z*c4.z + e0.w*c4.w;
        float nn0  = e0.x*e0.x + e0.y*e0.y + e0.z*e0.z + e0.w*e0.w;
        float num1 = e1.x*c4.x + e1.y*c4.y + e1.z*c4.z + e1.w*c4.w;
        float nn1  = e1.x*e1.x + e1.y*e1.y + e1.z*e1.z + e1.w*e1.w;
        #pragma unroll
        for (int o = 16; o; o >>= 1) {
            num0 += __shfl_down_sync(0xffffffffu, num0, o);
            nn0  += __shfl_down_sync(0xffffffffu, nn0,  o);
            num1 += __shfl_down_sync(0xffffffffu, num1, o);
            nn1  += __shfl_down_sync(0xffffffffu, nn1,  o);
        }
        if (lane == 0) {
            s_sim[n] = num0 / fmaxf(cn * sqrtf(nn0), 1e-8f);
            if (h1) s_sim[n1] = num1 / fmaxf(cn * sqrtf(nn1), 1e-8f);
        }
    }
    __syncthreads();

    // top-K with jax.lax.top_k tie-break (lower index wins); rank is a permutation
    if (t < MCAND) {
        const float v = s_sim[t];
        int r = 0;
        for (int i = 0; i < MCAND; i++) {
            const float u = s_sim[i];
            r += (u > v) || (u == v && i < t);
        }
        if (r < KSEL) { s_selr[r] = s_ridx[t]; s_sele[r] = s_eidx[t]; }
    }
    __syncthreads();

    {
        float acc = 0.f;
        if (t < DD) {
            #pragma unroll 8
            for (int k = 0; k < KSEL; k++) acc += emb[(size_t)s_selr[k] * DD + t];
        } else {
            const int d = t - DD;
            #pragma unroll 8
            for (int k = 0; k < KSEL; k++) acc += emb[(size_t)s_sele[k] * DD + d];
        }
        g_mcat[(size_t)tt * DMM + t] = acc * (1.f / KSEL);
    }
}

// ---------------- tf32 tensor-core GEMM: C[M,N] = A[M,K] @ B[N,K]^T ----------------
// Block tile 64 x NT (NT = 32 or 64), BK=32, 8 warps (2m x 4n), NJ = NT/32 n8-frags
// per warp. smem in FRAGMENT order; round-8 pipeline (STORE(kt+1); LOAD(kt+2);
// COMPUTE(kt); sync). NT=32 -> 24KB smem, 2 CTAs/SM (grid permitting) = 16 warps.
// EPI: 0 = +bias[n], 1 = relu(+bias[n]), 2 = +Cadd[m,n]+bias[n], 3 = raw (split-K),
//      4 = tanh(+bias[n]+Cadd[n]) scattered to g_cat,
//      5 = +bias[n], store C, AND fused LSTM step-0 (c0/hr; Cadd = qg)
template <int NT, int EPI>
__global__ __launch_bounds__(256, 2)
void tgemm(const float* __restrict__ A, const float* __restrict__ Bm,
           float* __restrict__ C, int M, int N, int K,
           const float* __restrict__ bias, const float* __restrict__ Cadd)
{
    constexpr int NI = 2;               // m16-frags per warp (MT=64 fixed)
    constexpr int NJ = NT / 32;         // n8-frags per warp (1 or 2)
    constexpr int LB = NT / 32;         // B loader row-passes
    __shared__ __align__(16) uint32_t As[2][2048];
    __shared__ __align__(16) uint32_t Bs[2][NT * 32];

    const int t    = threadIdx.x;
    const int lane = t & 31;
    const int w    = t >> 5;
    const int wm   = w >> 2;            // 0..1 (m half)
    const int wn   = w & 3;             // 0..3 (n slice)
    const int m0   = blockIdx.y * 64;
    const int n0   = blockIdx.x * NT;
    const int ksz  = K / gridDim.z;
    const int kb   = blockIdx.z * ksz;

    const int srow = t >> 3;            // 0..31
    const int k4   = t & 7;             // float4 index within BK=32
    const int ks_s = k4 >> 1;           // kstep 0..3
    const int jA   = (k4 & 1) * 2;
    const int jB   = (k4 & 1);

    float acc[NI][NJ][4];
    #pragma unroll
    for (int i = 0; i < NI; i++)
        #pragma unroll
        for (int j = 0; j < NJ; j++)
            #pragma unroll
            for (int q = 0; q < 4; q++) acc[i][j][q] = 0.f;

    const float4 z4 = make_float4(0.f, 0.f, 0.f, 0.f);
    float4 ga[2], gb[LB];

    #define TLOAD(kt)                                                          \
        { _Pragma("unroll")                                                    \
          for (int p = 0; p < 2; p++) {                                        \
            const int m = m0 + p * 32 + srow;                                  \
            ga[p] = (m < M) ? *(const float4*)(A + (size_t)m * K + kb + (kt)*32 + k4*4) : z4; \
          }                                                                     \
          _Pragma("unroll")                                                    \
          for (int p = 0; p < LB; p++) {                                       \
            const int rr = p * 32 + srow;                                      \
            gb[p] = *(const float4*)(Bm + (size_t)(n0 + rr) * K + kb + (kt)*32 + k4*4); \
          } }

    #define TSTORE(buf)                                                        \
        { _Pragma("unroll")                                                    \
          for (int p = 0; p < 2; p++) {                                        \
            const int rr = p * 32 + srow;                                      \
            const int mt = rr >> 4, rr16 = rr & 15;                            \
            const int lbA = (rr16 & 7) * 4;                                    \
            const int jjA = (rr16 >> 3) + jA;                                  \
            uint32_t* da = &As[buf][(mt*4 + ks_s)*128 + jjA];                  \
            da[(lbA+0)*4] = f2tf(ga[p].x); da[(lbA+1)*4] = f2tf(ga[p].y);      \
            da[(lbA+2)*4] = f2tf(ga[p].z); da[(lbA+3)*4] = f2tf(ga[p].w);      \
          }                                                                     \
          _Pragma("unroll")                                                    \
          for (int p = 0; p < LB; p++) {                                       \
            const int rr = p * 32 + srow;                                      \
            const int nt = rr >> 3, nn8 = rr & 7;                              \
            uint32_t* db = &Bs[buf][(nt*4 + ks_s)*64 + jB];                    \
            db[(nn8*4+0)*2] = f2tf(gb[p].x); db[(nn8*4+1)*2] = f2tf(gb[p].y);  \
            db[(nn8*4+2)*2] = f2tf(gb[p].z); db[(nn8*4+3)*2] = f2tf(gb[p].w);  \
          } }

    const int nkt = ksz >> 5;
    TLOAD(0);
    TSTORE(0);
    if (nkt > 1) TLOAD(1);
    __syncthreads();

    for (int kt = 0; kt < nkt; kt++) {
        const int cur = kt & 1;
        if (kt + 1 < nkt) TSTORE(cur ^ 1);
        if (kt + 2 < nkt) TLOAD(kt + 2);
        #pragma unroll
        for (int ks = 0; ks < 4; ks++) {
            uint4 afr[NI];
            uint2 bfr[NJ];
            #pragma unroll
            for (int i = 0; i < NI; i++)
                afr[i] = *(const uint4*)&As[cur][((wm*NI + i)*4 + ks)*128 + lane*4];
            #pragma unroll
            for (int j = 0; j < NJ; j++)
                bfr[j] = *(const uint2*)&Bs[cur][((wn*NJ + j)*4 + ks)*64 + lane*2];
            #pragma unroll
            for (int i = 0; i < NI; i++)
                #pragma unroll
                for (int j = 0; j < NJ; j++)
                    mma8(acc[i][j], afr[i], bfr[j]);
        }
        if (kt + 1 < nkt) __syncthreads();
    }
    #undef TLOAD
    #undef TSTORE

    C += (size_t)blockIdx.z * M * N;
    const int mr  = lane >> 2;
    const int nc  = (lane & 3) * 2;
    #pragma unroll
    for (int i = 0; i < NI; i++) {
        #pragma unroll
        for (int j = 0; j < NJ; j++) {
            const int mrow = m0 + wm*32 + i*16 + mr;
            const int ncol = n0 + wn*(8*NJ) + j*8 + nc;
            if (EPI == 4) {
                const float2 bb = *(const float2*)(bias + ncol);
                const float2 cc = *(const float2*)(Cadd + ncol);
                #pragma unroll
                for (int q = 0; q < 2; q++) {
                    const int mm = mrow + q * 8;
                    if (mm < M) {
                        const int r    = (mm < RTOT) ? mm : mm - RTOT;
                        const int coff = (mm < RTOT) ? 0 : DD;
                        float2 v;
                        v.x = tanhf(acc[i][j][q*2+0] + bb.x + cc.x);
                        v.y = tanhf(acc[i][j][q*2+1] + bb.y + cc.y);
                        *(float2*)(g_cat + (size_t)r * DMM + coff + ncol) = v;
                    }
                }
                continue;
            }
            float2 bv = make_float2(0.f, 0.f);
            if (EPI != 3) bv = *(const float2*)(bias + ncol);
            float2 v0 = make_float2(acc[i][j][0] + bv.x, acc[i][j][1] + bv.y);
            float2 v1 = make_float2(acc[i][j][2] + bv.x, acc[i][j][3] + bv.y);
            if (EPI == 5) {
                if (mrow < M)     *(float2*)(C + (size_t)mrow * N + ncol) = v0;
                if (mrow + 8 < M) *(float2*)(C + (size_t)(mrow + 8) * N + ncol) = v1;
                const float rx0 = __shfl_xor_sync(0xffffffffu, v0.x, 1);
                const float ry0 = __shfl_xor_sync(0xffffffffu, v0.y, 1);
                const float rx1 = __shfl_xor_sync(0xffffffffu, v1.x, 1);
                const float ry1 = __shfl_xor_sync(0xffffffffu, v1.y, 1);
                (void)ry1;
                const int jj = ncol >> 2;
                int myrow; float gi, gg, go;
                if ((lane & 1) == 0) { myrow = mrow;     gi = v0.x; gg = rx0;  go = ry0;  }
                else                 { myrow = mrow + 8; gi = rx1;  gg = v1.x; go = v1.y; }
                if (myrow < M) {
                    const float c0 = sigf(gi) * tanhf(gg);
                    const float h  = Cadd[(size_t)myrow * DMM + jj] + sigf(go) * tanhf(c0);
                    g_c0[(size_t)myrow * DMM + jj] = c0;
                    g_hr[(size_t)myrow * DMM + jj] = h;
                }
                continue;
            }
            if (EPI == 1) {
                v0.x = fmaxf(v0.x, 0.f); v0.y = fmaxf(v0.y, 0.f);
                v1.x = fmaxf(v1.x, 0.f); v1.y = fmaxf(v1.y, 0.f);
            }
            if (EPI == 2) {
                if (mrow < M) {
                    float2 c0 = *(const float2*)(Cadd + (size_t)mrow * N + ncol);
                    v0.x += c0.x; v0.y += c0.y;
                }
                if (mrow + 8 < M) {
                    float2 c1 = *(const float2*)(Cadd + (size_t)(mrow + 8) * N + ncol);
                    v1.x += c1.x; v1.y += c1.y;
                }
            }
            if (mrow < M)     *(float2*)(C + (size_t)mrow * N + ncol) = v0;
            if (mrow + 8 < M) *(float2*)(C + (size_t)(mrow + 8) * N + ncol) = v1;
        }
    }
}

// ---------------- residual + layernorm (sums the 2 split-K planes + b2) ----------------
__global__ __launch_bounds__(256)
void ln_kernel(const float* __restrict__ g, const float* __restrict__ b,
               const float* __restrict__ b2)
{
    const int row = blockIdx.x;
    const int t = threadIdx.x;
    const int lane = t & 31, w = t >> 5;
    const float x = g_cat[(size_t)row * DMM + t];
    const float y = g_h2[(size_t)row * DMM + t]
                  + g_h2[(size_t)(RTOT + row) * DMM + t]
                  + b2[t] + x;

    __shared__ float s1[8], s2[8];
    __shared__ float s_mu, s_rs;
    float s = y, ss = y * y;
    #pragma unroll
    for (int o = 16; o; o >>= 1) {
        s  += __shfl_down_sync(0xffffffffu, s,  o);
        ss += __shfl_down_sync(0xffffffffu, ss, o);
    }
    if (lane == 0) { s1[w] = s; s2[w] = ss; }
    __syncthreads();
    if (t == 0) {
        float S = 0.f, SS = 0.f;
        #pragma unroll
        for (int i = 0; i < 8; i++) { S += s1[i]; SS += s2[i]; }
        const float mu = S / DMM;
        const float var = SS / DMM - mu * mu;
        s_mu = mu; s_rs = rsqrtf(var + 1e-5f);
    }
    __syncthreads();
    const float o = g[t] * (y - s_mu) * s_rs + b[t];
    if (row < NQ) g_qg[(size_t)row * DMM + t] = o;
    else          g_sse[(size_t)(row - NQ) * DMM + t] = o;
}

// ---------------- LSTM step 1 + l2norm + final dot (interleaved gates) ----------------
__global__ __launch_bounds__(256)
void final_kernel(float* __restrict__ out)
{
    const int row = blockIdx.x;
    const int t = threadIdx.x;
    const int lane = t & 31, w = t >> 5;
    const float4 g4 = *(const float4*)(g_gates + (size_t)row * GC + t * 4);
    const float ig = sigf(g4.x);
    const float fg = sigf(g4.y);
    const float gg = tanhf(g4.z);
    const float og = sigf(g4.w);
    const float c  = fg * g_c0[(size_t)row * DMM + t] + ig * gg;
    const float h  = g_qg[(size_t)row * DMM + t] + og * tanhf(c);

    float d = h * g_sgn[t];
    float n2 = h * h;
    __shared__ float sd[8], sn[8];
    #pragma unroll
    for (int o = 16; o; o >>= 1) {
        d  += __shfl_down_sync(0xffffffffu, d,  o);
        n2 += __shfl_down_sync(0xffffffffu, n2, o);
    }
    if (lane == 0) { sd[w] = d; sn[w] = n2; }
    __syncthreads();
    if (t == 0) {
        float DT = 0.f, NT2 = 0.f;
        #pragma unroll
        for (int i = 0; i < 8; i++) { DT += sd[i]; NT2 += sn[i]; }
        out[row] = DT / fmaxf(sqrtf(NT2), 1e-12f);
    }
}

// ---------------- launch ----------------
extern "C" void kernel_launch(void* const* d_in, const int* in_sizes, int n_in,
                              void* d_out, int out_size)
{
    const int*   query   = (const int*)  d_in[0];
    const int*   support = (const int*)  d_in[1];
    const int*   qlc     = (const int*)  d_in[2];
    const int*   qrc     = (const int*)  d_in[4];
    const int*   slc     = (const int*)  d_in[6];
    const int*   src     = (const int*)  d_in[8];
    const float* emb     = (const float*)d_in[10];
    const float* gcnW    = (const float*)d_in[11];
    const float* gbias   = (const float*)d_in[12];
    const float* gb      = (const float*)d_in[13];
    const float* w1      = (const float*)d_in[14];
    const float* b1      = (const float*)d_in[15];
    const float* w2      = (const float*)d_in[16];
    const float* b2      = (const float*)d_in[17];
    const float* lng     = (const float*)d_in[18];
    const float* lnb     = (const float*)d_in[19];
    const float* Wih     = (const float*)d_in[20];
    const float* Whh     = (const float*)d_in[21];
    const float* bih     = (const float*)d_in[22];
    const float* bhh     = (const float*)d_in[23];
    float* out = (float*)d_out;

    float *p_mcat, *p_cat, *p_h1, *p_h2, *p_qg, *p_WihC, *p_WhhC, *p_bsumC, *p_svec;
    float *p_GxC, *p_gates, *p_hr;
    cudaGetSymbolAddress((void**)&p_mcat,  g_mcat);
    cudaGetSymbolAddress((void**)&p_cat,   g_cat);
    cudaGetSymbolAddress((void**)&p_h1,    g_h1);
    cudaGetSymbolAddress((void**)&p_h2,    g_h2);
    cudaGetSymbolAddress((void**)&p_qg,    g_qg);
    cudaGetSymbolAddress((void**)&p_WihC,  g_WihC);
    cudaGetSymbolAddress((void**)&p_WhhC,  g_WhhC);
    cudaGetSymbolAddress((void**)&p_bsumC, g_bsumC);
    cudaGetSymbolAddress((void**)&p_svec,  g_svec);
    cudaGetSymbolAddress((void**)&p_GxC,   g_GxC);
    cudaGetSymbolAddress((void**)&p_gates, g_gates);
    cudaGetSymbolAddress((void**)&p_hr,    g_hr);

    compact_kernel<<<GC * DMM / 256, 256>>>(Wih, Whh, bih, bhh);
    neighbor_all<<<NBLK, 256>>>(emb, qlc, qrc, slc, src, query, support);

    // gcn projection: g_cat = tanh(mcat @ gcnW^T + gbias + gb), scattered layout
    tgemm<32, 4><<<dim3(DD / 32, (NBLK + 63) / 64), 256>>>(p_mcat, gcnW, nullptr, NBLK, DD, DMM, gbias, gb);

    // support encoder (batched query + support rows)
    tgemm<32, 1><<<dim3(DFF / 32, (RTOT + 63) / 64), 256>>>(p_cat, w1, p_h1, RTOT, DFF, DMM, b1, nullptr);
    tgemm<32, 3><<<dim3(DMM / 32, (RTOT + 63) / 64, 2), 256>>>(p_h1, w2, p_h2, RTOT, DMM, DFF, nullptr, nullptr);
    ln_kernel<<<RTOT, 256>>>(lng, lnb, b2);
    svec_kernel<<<GC / 8, 256>>>(Whh);

    // query encoder: Gx GEMM with fused LSTM step-0 (EPI 5, Cadd = qg)
    tgemm<32, 5><<<dim3(GC / 32, NQ / 64), 256>>>(p_qg, p_WihC, p_GxC, NQ, GC, DMM, p_bsumC, p_qg);
    tgemm<32, 2><<<dim3(GC / 32, NQ / 64), 256>>>(p_hr, p_WhhC, p_gates, NQ, GC, DMM, p_svec, p_GxC);
    final_kernel<<<NQ, 256>>>(out);
}

// round 12
// speedup vs baseline: 1.1397x; 1.1397x over previous
#include <cuda_runtime.h>
#include <math.h>
#include <stdint.h>

#define NQ    1024
#define FEWS  5
#define MCAND 200
#define KSEL  32
#define DD    128
#define DMM   256
#define DFF   512
#define HHH   512
#define GC    1024            // compacted gate columns, interleaved (j*4 + gate)
#define RTOT  (NQ + FEWS)     // 1029
#define NBLK  (2*NQ + 2*FEWS) // 2058 neighbor tasks

// ---------------- workspace (device globals; no allocations) ----------------
__device__ float g_mcat [NBLK * DMM];       // per-task K-mean [rel;ent]
__device__ float g_cat  [RTOT * DMM];
__device__ float g_h1   [RTOT * DFF];
__device__ float g_h2   [2 * RTOT * DMM];   // 2 split-K planes
__device__ float g_qg   [NQ   * DMM];
__device__ float g_sse  [FEWS * DMM];
__device__ float g_sgn  [DMM];
__device__ float g_WihC [GC * DMM];
__device__ float g_WhhC [GC * DMM];
__device__ float g_bsumC[GC];
__device__ float g_svec [GC];
__device__ float g_GxC  [NQ * GC];
__device__ float g_gates[NQ * GC];
__device__ float g_c0   [NQ * DMM];
__device__ float g_hr   [NQ * DMM];

// interleaved gate col r -> original 4H row: gate = r&3, j = r>>2, o = gate*512 + j
__device__ __forceinline__ int orig_col(int r) { return (r & 3) * 512 + (r >> 2); }

__device__ __forceinline__ float sigf(float x) { return 1.f / (1.f + expf(-x)); }

__device__ __forceinline__ uint32_t f2tf(float x) {
    uint32_t r;
    asm("cvt.rna.tf32.f32 %0, %1;" : "=r"(r) : "f"(x));
    return r;
}

__device__ __forceinline__ void mma8(float* c, const uint4& a, const uint2& b) {
    asm volatile(
        "mma.sync.aligned.m16n8k8.row.col.f32.tf32.tf32.f32 "
        "{%0,%1,%2,%3}, {%4,%5,%6,%7}, {%8,%9}, {%0,%1,%2,%3};"
        : "+f"(c[0]), "+f"(c[1]), "+f"(c[2]), "+f"(c[3])
        : "r"(a.x), "r"(a.y), "r"(a.z), "r"(a.w), "r"(b.x), "r"(b.y));
}

// ---------------- weight compaction: live gate columns, interleaved ----------------
__global__ __launch_bounds__(256)
void compact_kernel(const float* __restrict__ Wih, const float* __restrict__ Whh,
                    const float* __restrict__ bih, const float* __restrict__ bhh)
{
    const int idx = blockIdx.x * 256 + threadIdx.x;   // GC*DMM threads
    const int r = idx >> 8, c = idx & 255;
    const int o = orig_col(r);
    g_WihC[idx] = Wih[(size_t)o * DMM + c];
    g_WhhC[idx] = Whh[(size_t)o * HHH + c];
    if (c == 0) g_bsumC[r] = bih[o] + bhh[o];
}

// ---------------- svec + support mean + sgn (merged) ----------------
__global__ __launch_bounds__(256)
void svec_kernel(const float* __restrict__ Whh)
{
    const int t = threadIdx.x;
    const int lane = t & 31, w = t >> 5;
    __shared__ float ssg[DMM];
    __shared__ float s1[8];
    __shared__ float s_n;

    float s = 0.f;
    #pragma unroll
    for (int r = 0; r < FEWS; r++) s += g_sse[r * DMM + t];
    ssg[t] = s * (1.f / FEWS);
    __syncthreads();

    const int r = blockIdx.x * 8 + w;      // grid 128 -> 1024 warps
    const int o = orig_col(r);
    const float* wr = Whh + (size_t)o * HHH + DMM;
    float p = 0.f;
    #pragma unroll
    for (int c = lane; c < DMM; c += 32) p += wr[c] * ssg[c];
    #pragma unroll
    for (int off = 16; off; off >>= 1) p += __shfl_down_sync(0xffffffffu, p, off);
    if (lane == 0) g_svec[r] = p;

    if (blockIdx.x == 0) {
        __syncthreads();
        float q = ssg[t] * ssg[t];
        #pragma unroll
        for (int off = 16; off; off >>= 1) q += __shfl_down_sync(0xffffffffu, q, off);
        if (lane == 0) s1[w] = q;
        __syncthreads();
        if (t == 0) {
            float S = 0.f;
            #pragma unroll
            for (int i = 0; i < 8; i++) S += s1[i];
            s_n = fmaxf(sqrtf(S), 1e-12f);
        }
        __syncthreads();
        g_sgn[t] = ssg[t] / s_n;
    }
}

// ---------------- neighbor encoder: sims + top-K + mean only ----------------
__global__ __launch_bounds__(256)
void neighbor_all(const float* __restrict__ emb,
                  const int* __restrict__ qlc, const int* __restrict__ qrc,
                  const int* __restrict__ slc, const int* __restrict__ src,
                  const int* __restrict__ query, const int* __restrict__ support)
{
    const int b = blockIdx.x;
    const int t = threadIdx.x;
    const int lane = t & 31;
    const int w = t >> 5;

    const int* conn_row;
    int cid, tt;
    if (b < NQ)            { conn_row = qlc + (size_t)b * MCAND * 2;                 cid = query[b * 2 + 0];   tt = b; }
    else if (b < 2 * NQ)   { int rb = b - NQ;        conn_row = qrc + (size_t)rb * MCAND * 2; cid = query[rb * 2 + 1];   tt = RTOT + rb; }
    else if (b < 2*NQ+FEWS){ int rb = b - 2*NQ;      conn_row = slc + (size_t)rb * MCAND * 2; cid = support[rb*2 + 0];   tt = NQ + rb; }
    else                   { int rb = b - 2*NQ-FEWS; conn_row = src + (size_t)rb * MCAND * 2; cid = support[rb*2 + 1];   tt = RTOT + NQ + rb; }

    __shared__ __align__(16) float s_center[DD];
    __shared__ float s_sim [MCAND];
    __shared__ int   s_ridx[MCAND];
    __shared__ int   s_eidx[MCAND];
    __shared__ int   s_selr[KSEL];
    __shared__ int   s_sele[KSEL];
    __shared__ float s_red[8];
    __shared__ float s_cn;

    for (int n = t; n < MCAND; n += 256) {
        s_ridx[n] = conn_row[n * 2 + 0];
        s_eidx[n] = conn_row[n * 2 + 1];
    }
    float cv = 0.f;
    if (t < DD) { cv = emb[(size_t)cid * DD + t]; s_center[t] = cv; }

    float p = cv * cv;
    #pragma unroll
    for (int o = 16; o; o >>= 1) p += __shfl_down_sync(0xffffffffu, p, o);
    if (lane == 0) s_red[w] = p;
    __syncthreads();
    if (t == 0) {
        float s = 0.f;
        #pragma unroll
        for (int i = 0; i < 8; i++) s += s_red[i];
        s_cn = sqrtf(s);
    }
    __syncthreads();
    const float cn = s_cn;

    // cosine sims: warp handles 4 neighbors per iteration (4x MLP, 8 interleaved
    // shfl-reduction chains to amortize the 26-cyc SHFL latency)
    const float4 z4 = make_float4(0.f, 0.f, 0.f, 0.f);
    const float4 c4 = *(const float4*)(s_center + lane * 4);
    for (int nb = w; nb < MCAND; nb += 32) {
        int   ni[4];
        bool  va[4];
        float4 e[4];
        #pragma unroll
        for (int q = 0; q < 4; q++) {
            ni[q] = nb + q * 8;
            va[q] = ni[q] < MCAND;
            e[q]  = va[q] ? *(const float4*)(emb + (size_t)s_eidx[ni[q]] * DD + lane * 4) : z4;
        }
        float num[4], nrm[4];
        #pragma unroll
        for (int q = 0; q < 4; q++) {
            num[q] = e[q].x*c4.x + e[q].y*c4.y + e[q].z*c4.z + e[q].w*c4.w;
            nrm[q] = e[q].x*e[q].x + e[q].y*e[q].y + e[q].z*e[q].z + e[q].w*e[q].w;
        }
        #pragma unroll
        for (int o = 16; o; o >>= 1) {
            #pragma unroll
            for (int q = 0; q < 4; q++) {
                num[q] += __shfl_down_sync(0xffffffffu, num[q], o);
                nrm[q] += __shfl_down_sync(0xffffffffu, nrm[q], o);
            }
        }
        if (lane == 0) {
            #pragma unroll
            for (int q = 0; q < 4; q++)
                if (va[q]) s_sim[ni[q]] = num[q] / fmaxf(cn * sqrtf(nrm[q]), 1e-8f);
        }
    }
    __syncthreads();

    // top-K with jax.lax.top_k tie-break (lower index wins); rank is a permutation
    if (t < MCAND) {
        const float v = s_sim[t];
        int r = 0;
        for (int i = 0; i < MCAND; i++) {
            const float u = s_sim[i];
            r += (u > v) || (u == v && i < t);
        }
        if (r < KSEL) { s_selr[r] = s_ridx[t]; s_sele[r] = s_eidx[t]; }
    }
    __syncthreads();

    {
        float acc = 0.f;
        if (t < DD) {
            #pragma unroll 8
            for (int k = 0; k < KSEL; k++) acc += emb[(size_t)s_selr[k] * DD + t];
        } else {
            const int d = t - DD;
            #pragma unroll 8
            for (int k = 0; k < KSEL; k++) acc += emb[(size_t)s_sele[k] * DD + d];
        }
        g_mcat[(size_t)tt * DMM + t] = acc * (1.f / KSEL);
    }
}

// ---------------- tf32 tensor-core GEMM: C[M,N] = A[M,K] @ B[N,K]^T ----------------
// Block tile 64x64, BK=32, 8 warps (2m x 4n), warp tile 32x16 via m16n8k8 mma.
// Round-8 pipeline: STORE(kt+1); LOAD(kt+2); COMPUTE(kt); sync  (best measured).
// EPI: 0 = +bias[n], 1 = relu(+bias[n]), 2 = +Cadd[m,n]+bias[n], 3 = raw (split-K),
//      4 = tanh(+bias[n]+Cadd[n]) scattered to g_cat,
//      5 = +bias[n], store C, AND fused LSTM step-0 (c0/hr; Cadd = qg)
template <int EPI>
__global__ __launch_bounds__(256)
void tgemm(const float* __restrict__ A, const float* __restrict__ Bm,
           float* __restrict__ C, int M, int N, int K,
           const float* __restrict__ bias, const float* __restrict__ Cadd)
{
    __shared__ __align__(16) uint32_t As[2][2048];
    __shared__ __align__(16) uint32_t Bs[2][2048];

    const int t    = threadIdx.x;
    const int lane = t & 31;
    const int w    = t >> 5;
    const int wm   = w >> 2;
    const int wn   = w & 3;
    const int m0   = blockIdx.y * 64;
    const int n0   = blockIdx.x * 64;
    const int ksz  = K / gridDim.z;
    const int kb   = blockIdx.z * ksz;

    const int srow = t >> 3;
    const int k4   = t & 7;
    const int ks_s = k4 >> 1;
    const int jA   = (k4 & 1) * 2;
    const int jB   = (k4 & 1);

    float acc[2][2][4];
    #pragma unroll
    for (int i = 0; i < 2; i++)
        #pragma unroll
        for (int j = 0; j < 2; j++)
            #pragma unroll
            for (int q = 0; q < 4; q++) acc[i][j][q] = 0.f;

    const float4 z4 = make_float4(0.f, 0.f, 0.f, 0.f);
    float4 ga[2], gb[2];

    #define TLOAD(kt)                                                          \
        { _Pragma("unroll")                                                    \
          for (int p = 0; p < 2; p++) {                                        \
            const int rr = p * 32 + srow;                                      \
            const int m = m0 + rr;                                             \
            ga[p] = (m < M) ? *(const float4*)(A + (size_t)m * K + kb + (kt)*32 + k4*4) : z4; \
            gb[p] = *(const float4*)(Bm + (size_t)(n0 + rr) * K + kb + (kt)*32 + k4*4);       \
          } }

    #define TSTORE(buf)                                                        \
        { _Pragma("unroll")                                                    \
          for (int p = 0; p < 2; p++) {                                        \
            const int rr = p * 32 + srow;                                      \
            const int mt = rr >> 4, rr16 = rr & 15;                            \
            const int lbA = (rr16 & 7) * 4;                                    \
            const int jjA = (rr16 >> 3) + jA;                                  \
            uint32_t* da = &As[buf][(mt*4 + ks_s)*128 + jjA];                  \
            da[(lbA+0)*4] = f2tf(ga[p].x); da[(lbA+1)*4] = f2tf(ga[p].y);      \
            da[(lbA+2)*4] = f2tf(ga[p].z); da[(lbA+3)*4] = f2tf(ga[p].w);      \
            const int nt = rr >> 3, nn8 = rr & 7;                              \
            uint32_t* db = &Bs[buf][(nt*4 + ks_s)*64 + jB];                    \
            db[(nn8*4+0)*2] = f2tf(gb[p].x); db[(nn8*4+1)*2] = f2tf(gb[p].y);  \
            db[(nn8*4+2)*2] = f2tf(gb[p].z); db[(nn8*4+3)*2] = f2tf(gb[p].w);  \
          } }

    const int nkt = ksz >> 5;
    TLOAD(0);
    TSTORE(0);
    if (nkt > 1) TLOAD(1);
    __syncthreads();

    for (int kt = 0; kt < nkt; kt++) {
        const int cur = kt & 1;
        if (kt + 1 < nkt) TSTORE(cur ^ 1);
        if (kt + 2 < nkt) TLOAD(kt + 2);
        #pragma unroll
        for (int ks = 0; ks < 4; ks++) {
            uint4 afr[2];
            uint2 bfr[2];
            #pragma unroll
            for (int i = 0; i < 2; i++)
                afr[i] = *(const uint4*)&As[cur][((wm*2 + i)*4 + ks)*128 + lane*4];
            #pragma unroll
            for (int j = 0; j < 2; j++)
                bfr[j] = *(const uint2*)&Bs[cur][((wn*2 + j)*4 + ks)*64 + lane*2];
            #pragma unroll
            for (int i = 0; i < 2; i++)
                #pragma unroll
                for (int j = 0; j < 2; j++)
                    mma8(acc[i][j], afr[i], bfr[j]);
        }
        if (kt + 1 < nkt) __syncthreads();
    }
    #undef TLOAD
    #undef TSTORE

    C += (size_t)blockIdx.z * M * N;
    const int mr  = lane >> 2;
    const int nc  = (lane & 3) * 2;
    #pragma unroll
    for (int i = 0; i < 2; i++) {
        #pragma unroll
        for (int j = 0; j < 2; j++) {
            const int mrow = m0 + wm*32 + i*16 + mr;
            const int ncol = n0 + wn*16 + j*8 + nc;
            if (EPI == 4) {
                const float2 bb = *(const float2*)(bias + ncol);
                const float2 cc = *(const float2*)(Cadd + ncol);
                #pragma unroll
                for (int q = 0; q < 2; q++) {
                    const int mm = mrow + q * 8;
                    if (mm < M) {
                        const int r    = (mm < RTOT) ? mm : mm - RTOT;
                        const int coff = (mm < RTOT) ? 0 : DD;
                        float2 v;
                        v.x = tanhf(acc[i][j][q*2+0] + bb.x + cc.x);
                        v.y = tanhf(acc[i][j][q*2+1] + bb.y + cc.y);
                        *(float2*)(g_cat + (size_t)r * DMM + coff + ncol) = v;
                    }
                }
                continue;
            }
            float2 bv = make_float2(0.f, 0.f);
            if (EPI != 3) bv = *(const float2*)(bias + ncol);
            float2 v0 = make_float2(acc[i][j][0] + bv.x, acc[i][j][1] + bv.y);
            float2 v1 = make_float2(acc[i][j][2] + bv.x, acc[i][j][3] + bv.y);
            if (EPI == 5) {
                if (mrow < M)     *(float2*)(C + (size_t)mrow * N + ncol) = v0;
                if (mrow + 8 < M) *(float2*)(C + (size_t)(mrow + 8) * N + ncol) = v1;
                const float rx0 = __shfl_xor_sync(0xffffffffu, v0.x, 1);
                const float ry0 = __shfl_xor_sync(0xffffffffu, v0.y, 1);
                const float rx1 = __shfl_xor_sync(0xffffffffu, v1.x, 1);
                const float ry1 = __shfl_xor_sync(0xffffffffu, v1.y, 1);
                (void)ry1;
                const int jj = ncol >> 2;
                int myrow; float gi, gg, go;
                if ((lane & 1) == 0) { myrow = mrow;     gi = v0.x; gg = rx0;  go = ry0;  }
                else                 { myrow = mrow + 8; gi = rx1;  gg = v1.x; go = v1.y; }
                if (myrow < M) {
                    const float c0 = sigf(gi) * tanhf(gg);
                    const float h  = Cadd[(size_t)myrow * DMM + jj] + sigf(go) * tanhf(c0);
                    g_c0[(size_t)myrow * DMM + jj] = c0;
                    g_hr[(size_t)myrow * DMM + jj] = h;
                }
                continue;
            }
            if (EPI == 1) {
                v0.x = fmaxf(v0.x, 0.f); v0.y = fmaxf(v0.y, 0.f);
                v1.x = fmaxf(v1.x, 0.f); v1.y = fmaxf(v1.y, 0.f);
            }
            if (EPI == 2) {
                if (mrow < M) {
                    float2 c0 = *(const float2*)(Cadd + (size_t)mrow * N + ncol);
                    v0.x += c0.x; v0.y += c0.y;
                }
                if (mrow + 8 < M) {
                    float2 c1 = *(const float2*)(Cadd + (size_t)(mrow + 8) * N + ncol);
                    v1.x += c1.x; v1.y += c1.y;
                }
            }
            if (mrow < M)     *(float2*)(C + (size_t)mrow * N + ncol) = v0;
            if (mrow + 8 < M) *(float2*)(C + (size_t)(mrow + 8) * N + ncol) = v1;
        }
    }
}

// ---------------- residual + layernorm (sums the 2 split-K planes + b2) ----------------
__global__ __launch_bounds__(256)
void ln_kernel(const float* __restrict__ g, const float* __restrict__ b,
               const float* __restrict__ b2)
{
    const int row = blockIdx.x;
    const int t = threadIdx.x;
    const int lane = t & 31, w = t >> 5;
    const float x = g_cat[(size_t)row * DMM + t];
    const float y = g_h2[(size_t)row * DMM + t]
                  + g_h2[(size_t)(RTOT + row) * DMM + t]
                  + b2[t] + x;

    __shared__ float s1[8], s2[8];
    __shared__ float s_mu, s_rs;
    float s = y, ss = y * y;
    #pragma unroll
    for (int o = 16; o; o >>= 1) {
        s  += __shfl_down_sync(0xffffffffu, s,  o);
        ss += __shfl_down_sync(0xffffffffu, ss, o);
    }
    if (lane == 0) { s1[w] = s; s2[w] = ss; }
    __syncthreads();
    if (t == 0) {
        float S = 0.f, SS = 0.f;
        #pragma unroll
        for (int i = 0; i < 8; i++) { S += s1[i]; SS += s2[i]; }
        const float mu = S / DMM;
        const float var = SS / DMM - mu * mu;
        s_mu = mu; s_rs = rsqrtf(var + 1e-5f);
    }
    __syncthreads();
    const float o = g[t] * (y - s_mu) * s_rs + b[t];
    if (row < NQ) g_qg[(size_t)row * DMM + t] = o;
    else          g_sse[(size_t)(row - NQ) * DMM + t] = o;
}

// ---------------- LSTM step 1 + l2norm + final dot (interleaved gates) ----------------
__global__ __launch_bounds__(256)
void final_kernel(float* __restrict__ out)
{
    const int row = blockIdx.x;
    const int t = threadIdx.x;
    const int lane = t & 31, w = t >> 5;
    const float4 g4 = *(const float4*)(g_gates + (size_t)row * GC + t * 4);
    const float ig = sigf(g4.x);
    const float fg = sigf(g4.y);
    const float gg = tanhf(g4.z);
    const float og = sigf(g4.w);
    const float c  = fg * g_c0[(size_t)row * DMM + t] + ig * gg;
    const float h  = g_qg[(size_t)row * DMM + t] + og * tanhf(c);

    float d = h * g_sgn[t];
    float n2 = h * h;
    __shared__ float sd[8], sn[8];
    #pragma unroll
    for (int o = 16; o; o >>= 1) {
        d  += __shfl_down_sync(0xffffffffu, d,  o);
        n2 += __shfl_down_sync(0xffffffffu, n2, o);
    }
    if (lane == 0) { sd[w] = d; sn[w] = n2; }
    __syncthreads();
    if (t == 0) {
        float DT = 0.f, NT = 0.f;
        #pragma unroll
        for (int i = 0; i < 8; i++) { DT += sd[i]; NT += sn[i]; }
        out[row] = DT / fmaxf(sqrtf(NT), 1e-12f);
    }
}

// ---------------- launch ----------------
extern "C" void kernel_launch(void* const* d_in, const int* in_sizes, int n_in,
                              void* d_out, int out_size)
{
    const int*   query   = (const int*)  d_in[0];
    const int*   support = (const int*)  d_in[1];
    const int*   qlc     = (const int*)  d_in[2];
    const int*   qrc     = (const int*)  d_in[4];
    const int*   slc     = (const int*)  d_in[6];
    const int*   src     = (const int*)  d_in[8];
    const float* emb     = (const float*)d_in[10];
    const float* gcnW    = (const float*)d_in[11];
    const float* gbias   = (const float*)d_in[12];
    const float* gb      = (const float*)d_in[13];
    const float* w1      = (const float*)d_in[14];
    const float* b1      = (const float*)d_in[15];
    const float* w2      = (const float*)d_in[16];
    const float* b2      = (const float*)d_in[17];
    const float* lng     = (const float*)d_in[18];
    const float* lnb     = (const float*)d_in[19];
    const float* Wih     = (const float*)d_in[20];
    const float* Whh     = (const float*)d_in[21];
    const float* bih     = (const float*)d_in[22];
    const float* bhh     = (const float*)d_in[23];
    float* out = (float*)d_out;

    float *p_mcat, *p_cat, *p_h1, *p_h2, *p_qg, *p_WihC, *p_WhhC, *p_bsumC, *p_svec;
    float *p_GxC, *p_gates, *p_hr;
    cudaGetSymbolAddress((void**)&p_mcat,  g_mcat);
    cudaGetSymbolAddress((void**)&p_cat,   g_cat);
    cudaGetSymbolAddress((void**)&p_h1,    g_h1);
    cudaGetSymbolAddress((void**)&p_h2,    g_h2);
    cudaGetSymbolAddress((void**)&p_qg,    g_qg);
    cudaGetSymbolAddress((void**)&p_WihC,  g_WihC);
    cudaGetSymbolAddress((void**)&p_WhhC,  g_WhhC);
    cudaGetSymbolAddress((void**)&p_bsumC, g_bsumC);
    cudaGetSymbolAddress((void**)&p_svec,  g_svec);
    cudaGetSymbolAddress((void**)&p_GxC,   g_GxC);
    cudaGetSymbolAddress((void**)&p_gates, g_gates);
    cudaGetSymbolAddress((void**)&p_hr,    g_hr);

    compact_kernel<<<GC * DMM / 256, 256>>>(Wih, Whh, bih, bhh);
    neighbor_all<<<NBLK, 256>>>(emb, qlc, qrc, slc, src, query, support);

    // gcn projection: g_cat = tanh(mcat @ gcnW^T + gbias + gb), scattered layout
    tgemm<4><<<dim3(DD / 64, (NBLK + 63) / 64), 256>>>(p_mcat, gcnW, nullptr, NBLK, DD, DMM, gbias, gb);

    // support encoder (batched query + support rows)
    tgemm<1><<<dim3(DFF / 64, (RTOT + 63) / 64), 256>>>(p_cat, w1, p_h1, RTOT, DFF, DMM, b1, nullptr);
    tgemm<3><<<dim3(DMM / 64, (RTOT + 63) / 64, 2), 256>>>(p_h1, w2, p_h2, RTOT, DMM, DFF, nullptr, nullptr);
    ln_kernel<<<RTOT, 256>>>(lng, lnb, b2);
    svec_kernel<<<GC / 8, 256>>>(Whh);

    // query encoder: Gx GEMM with fused LSTM step-0 (EPI 5, Cadd = qg)
    tgemm<5><<<dim3(GC / 64, NQ / 64), 256>>>(p_qg, p_WihC, p_GxC, NQ, GC, DMM, p_bsumC, p_qg);
    tgemm<2><<<dim3(GC / 64, NQ / 64), 256>>>(p_hr, p_WhhC, p_gates, NQ, GC, DMM, p_svec, p_GxC);
    final_kernel<<<NQ, 256>>>(out);
}

// round 14
// speedup vs baseline: 1.2856x; 1.1280x over previous
#include <cuda_runtime.h>
#include <math.h>
#include <stdint.h>

#define NQ    1024
#define FEWS  5
#define MCAND 200
#define KSEL  32
#define DD    128
#define DMM   256
#define DFF   512
#define HHH   512
#define GC    1024            // compacted gate columns, interleaved (j*4 + gate)
#define RTOT  (NQ + FEWS)     // 1029
#define NBLK  (2*NQ + 2*FEWS) // 2058 neighbor tasks

#define TG_STRIDE 36                      // floats per smem row (conflict-free, 16B-mult)
#define TG_TILEF  (64 * TG_STRIDE)        // floats per operand stage
#define TG_SMEM   (4 * 2 * TG_TILEF * 4)  // 4 stages x (A,B) x bytes = 73728

// ---------------- workspace (device globals; no allocations) ----------------
__device__ float g_mcat [NBLK * DMM];
__device__ float g_cat  [RTOT * DMM];
__device__ float g_h1   [RTOT * DFF];
__device__ float g_h2   [2 * RTOT * DMM];
__device__ float g_qg   [NQ   * DMM];
__device__ float g_sse  [FEWS * DMM];
__device__ float g_sgn  [DMM];
__device__ float g_WihC [GC * DMM];
__device__ float g_WhhC [GC * DMM];
__device__ float g_bsumC[GC];
__device__ float g_svec [GC];
__device__ float g_GxC  [NQ * GC];
__device__ float g_gates[NQ * GC];
__device__ float g_c0   [NQ * DMM];
__device__ float g_hr   [NQ * DMM];

__device__ __forceinline__ int orig_col(int r) { return (r & 3) * 512 + (r >> 2); }
__device__ __forceinline__ float sigf(float x) { return 1.f / (1.f + expf(-x)); }

__device__ __forceinline__ uint32_t f2tf(float x) {
    uint32_t r;
    asm("cvt.rna.tf32.f32 %0, %1;" : "=r"(r) : "f"(x));
    return r;
}

__device__ __forceinline__ void mma8(float* c, const uint4& a, const uint2& b) {
    asm volatile(
        "mma.sync.aligned.m16n8k8.row.col.f32.tf32.tf32.f32 "
        "{%0,%1,%2,%3}, {%4,%5,%6,%7}, {%8,%9}, {%0,%1,%2,%3};"
        : "+f"(c[0]), "+f"(c[1]), "+f"(c[2]), "+f"(c[3])
        : "r"(a.x), "r"(a.y), "r"(a.z), "r"(a.w), "r"(b.x), "r"(b.y));
}

// ---------------- weight compaction: live gate columns, interleaved ----------------
__global__ __launch_bounds__(256)
void compact_kernel(const float* __restrict__ Wih, const float* __restrict__ Whh,
                    const float* __restrict__ bih, const float* __restrict__ bhh)
{
    const int idx = blockIdx.x * 256 + threadIdx.x;
    const int r = idx >> 8, c = idx & 255;
    const int o = orig_col(r);
    g_WihC[idx] = Wih[(size_t)o * DMM + c];
    g_WhhC[idx] = Whh[(size_t)o * HHH + c];
    if (c == 0) g_bsumC[r] = bih[o] + bhh[o];
}

// ---------------- svec + support mean + sgn (merged) ----------------
__global__ __launch_bounds__(256)
void svec_kernel(const float* __restrict__ Whh)
{
    const int t = threadIdx.x;
    const int lane = t & 31, w = t >> 5;
    __shared__ float ssg[DMM];
    __shared__ float s1[8];
    __shared__ float s_n;

    float s = 0.f;
    #pragma unroll
    for (int r = 0; r < FEWS; r++) s += g_sse[r * DMM + t];
    ssg[t] = s * (1.f / FEWS);
    __syncthreads();

    const int r = blockIdx.x * 8 + w;
    const int o = orig_col(r);
    const float* wr = Whh + (size_t)o * HHH + DMM;
    float p = 0.f;
    #pragma unroll
    for (int c = lane; c < DMM; c += 32) p += wr[c] * ssg[c];
    #pragma unroll
    for (int off = 16; off; off >>= 1) p += __shfl_down_sync(0xffffffffu, p, off);
    if (lane == 0) g_svec[r] = p;

    if (blockIdx.x == 0) {
        __syncthreads();
        float q = ssg[t] * ssg[t];
        #pragma unroll
        for (int off = 16; off; off >>= 1) q += __shfl_down_sync(0xffffffffu, q, off);
        if (lane == 0) s1[w] = q;
        __syncthreads();
        if (t == 0) {
            float S = 0.f;
            #pragma unroll
            for (int i = 0; i < 8; i++) S += s1[i];
            s_n = fmaxf(sqrtf(S), 1e-12f);
        }
        __syncthreads();
        g_sgn[t] = ssg[t] / s_n;
    }
}

// ---------------- neighbor encoder: sims + top-K + mean only ----------------
__global__ __launch_bounds__(256)
void neighbor_all(const float* __restrict__ emb,
                  const int* __restrict__ qlc, const int* __restrict__ qrc,
                  const int* __restrict__ slc, const int* __restrict__ src,
                  const int* __restrict__ query, const int* __restrict__ support)
{
    const int b = blockIdx.x;
    const int t = threadIdx.x;
    const int lane = t & 31;
    const int w = t >> 5;

    const int* conn_row;
    int cid, tt;
    if (b < NQ)            { conn_row = qlc + (size_t)b * MCAND * 2;                 cid = query[b * 2 + 0];   tt = b; }
    else if (b < 2 * NQ)   { int rb = b - NQ;        conn_row = qrc + (size_t)rb * MCAND * 2; cid = query[rb * 2 + 1];   tt = RTOT + rb; }
    else if (b < 2*NQ+FEWS){ int rb = b - 2*NQ;      conn_row = slc + (size_t)rb * MCAND * 2; cid = support[rb*2 + 0];   tt = NQ + rb; }
    else                   { int rb = b - 2*NQ-FEWS; conn_row = src + (size_t)rb * MCAND * 2; cid = support[rb*2 + 1];   tt = RTOT + NQ + rb; }

    __shared__ __align__(16) float s_center[DD];
    __shared__ float s_sim [MCAND];
    __shared__ int   s_ridx[MCAND];
    __shared__ int   s_eidx[MCAND];
    __shared__ int   s_selr[KSEL];
    __shared__ int   s_sele[KSEL];
    __shared__ float s_red[8];
    __shared__ float s_cn;

    for (int n = t; n < MCAND; n += 256) {
        s_ridx[n] = conn_row[n * 2 + 0];
        s_eidx[n] = conn_row[n * 2 + 1];
    }
    float cv = 0.f;
    if (t < DD) { cv = emb[(size_t)cid * DD + t]; s_center[t] = cv; }

    float p = cv * cv;
    #pragma unroll
    for (int o = 16; o; o >>= 1) p += __shfl_down_sync(0xffffffffu, p, o);
    if (lane == 0) s_red[w] = p;
    __syncthreads();
    if (t == 0) {
        float s = 0.f;
        #pragma unroll
        for (int i = 0; i < 8; i++) s += s_red[i];
        s_cn = sqrtf(s);
    }
    __syncthreads();
    const float cn = s_cn;

    const float4 z4 = make_float4(0.f, 0.f, 0.f, 0.f);
    const float4 c4 = *(const float4*)(s_center + lane * 4);
    for (int nb = w; nb < MCAND; nb += 32) {
        int   ni[4];
        bool  va[4];
        float4 e[4];
        #pragma unroll
        for (int q = 0; q < 4; q++) {
            ni[q] = nb + q * 8;
            va[q] = ni[q] < MCAND;
            e[q]  = va[q] ? *(const float4*)(emb + (size_t)s_eidx[ni[q]] * DD + lane * 4) : z4;
        }
        float num[4], nrm[4];
        #pragma unroll
        for (int q = 0; q < 4; q++) {
            num[q] = e[q].x*c4.x + e[q].y*c4.y + e[q].z*c4.z + e[q].w*c4.w;
            nrm[q] = e[q].x*e[q].x + e[q].y*e[q].y + e[q].z*e[q].z + e[q].w*e[q].w;
        }
        #pragma unroll
        for (int o = 16; o; o >>= 1) {
            #pragma unroll
            for (int q = 0; q < 4; q++) {
                num[q] += __shfl_down_sync(0xffffffffu, num[q], o);
                nrm[q] += __shfl_down_sync(0xffffffffu, nrm[q], o);
            }
        }
        if (lane == 0) {
            #pragma unroll
            for (int q = 0; q < 4; q++)
                if (va[q]) s_sim[ni[q]] = num[q] / fmaxf(cn * sqrtf(nrm[q]), 1e-8f);
        }
    }
    __syncthreads();

    // top-K with jax.lax.top_k tie-break (lower index wins); rank is a permutation
    if (t < MCAND) {
        const float v = s_sim[t];
        int r = 0;
        for (int i = 0; i < MCAND; i++) {
            const float u = s_sim[i];
            r += (u > v) || (u == v && i < t);
        }
        if (r < KSEL) { s_selr[r] = s_ridx[t]; s_sele[r] = s_eidx[t]; }
    }
    __syncthreads();

    {
        float acc = 0.f;
        if (t < DD) {
            #pragma unroll 8
            for (int k = 0; k < KSEL; k++) acc += emb[(size_t)s_selr[k] * DD + t];
        } else {
            const int d = t - DD;
            #pragma unroll 8
            for (int k = 0; k < KSEL; k++) acc += emb[(size_t)s_sele[k] * DD + d];
        }
        g_mcat[(size_t)tt * DMM + t] = acc * (1.f / KSEL);
    }
}

// ---------------- tf32 tensor-core GEMM (cp.async pipeline) ----------------
// C[M,N] = A[M,K] @ B[N,K]^T. Block tile 64x64, BK=32, 8 warps (2m x 4n).
// 4-stage smem ring filled by cp.async.cg (16B), prefetch distance 2,
// wait_group + 1 barrier per ktile. Row-major smem, stride 36 (conflict-free
// fragment loads). Fragments converted with cvt.rna.tf32 AFTER the LDS
// (round-to-nearest; raw-bit truncation blew the error budget in R13).
// EPI: 0 = +bias[n], 1 = relu(+bias[n]), 2 = +Cadd[m,n]+bias[n], 3 = raw (split-K),
//      4 = tanh(+bias[n]+Cadd[n]) scattered to g_cat,
//      5 = +bias[n], store C, AND fused LSTM step-0 (c0/hr; Cadd = qg)
template <int EPI>
__global__ __launch_bounds__(256)
void tgemm(const float* __restrict__ A, const float* __restrict__ Bm,
           float* __restrict__ C, int M, int N, int K,
           const float* __restrict__ bias, const float* __restrict__ Cadd)
{
    extern __shared__ float smx[];
    const uint32_t smbase = (uint32_t)__cvta_generic_to_shared(smx);

    const int t    = threadIdx.x;
    const int lane = t & 31;
    const int w    = t >> 5;
    const int wm   = w >> 2;            // 0..1 (m half)
    const int wn   = w & 3;             // 0..3 (n 16-col slice)
    const int g    = lane >> 2;         // fragment group 0..7
    const int tig  = lane & 3;          // thread-in-group
    const int m0   = blockIdx.y * 64;
    const int n0   = blockIdx.x * 64;
    const int ksz  = K / gridDim.z;
    const int kb   = blockIdx.z * ksz;

    float acc[2][2][4];
    #pragma unroll
    for (int i = 0; i < 2; i++)
        #pragma unroll
        for (int j = 0; j < 2; j++)
            #pragma unroll
            for (int q = 0; q < 4; q++) acc[i][j][q] = 0.f;

    // issue one ktile's copies into stage (kt & 3); 4 cp.async per thread
    #define ISSUE(kt)                                                         \
        { const int stg = (kt) & 3;                                           \
          const uint32_t sA = smbase + (uint32_t)(stg * 2 * TG_TILEF) * 4u;   \
          const uint32_t sB = sA + (uint32_t)TG_TILEF * 4u;                   \
          _Pragma("unroll")                                                   \
          for (int p = 0; p < 2; p++) {                                       \
            const int c   = t + p * 256;                                      \
            const int row = c >> 3;                                           \
            const int ch  = (c & 7) * 4;                                      \
            const int m   = m0 + row;                                         \
            const int mc  = (m < M) ? m : (M - 1);                            \
            const int szA = (m < M) ? 16 : 0;                                 \
            const float* srcA = A + (size_t)mc * K + kb + (kt) * 32 + ch;     \
            const uint32_t dA = sA + (uint32_t)(row * TG_STRIDE + ch) * 4u;   \
            asm volatile("cp.async.cg.shared.global [%0], [%1], 16, %2;"      \
                         :: "r"(dA), "l"(srcA), "r"(szA));                    \
            const float* srcB = Bm + (size_t)(n0 + row) * K + kb + (kt)*32 + ch; \
            const uint32_t dB = sB + (uint32_t)(row * TG_STRIDE + ch) * 4u;   \
            asm volatile("cp.async.cg.shared.global [%0], [%1], 16;"          \
                         :: "r"(dB), "l"(srcB));                              \
          }                                                                    \
          asm volatile("cp.async.commit_group;" ::: "memory"); }

    #define TCOMP(kt)                                                         \
        { const int stg = (kt) & 3;                                           \
          const float* As_ = smx + stg * 2 * TG_TILEF;                        \
          const float* Bs_ = As_ + TG_TILEF;                                  \
          _Pragma("unroll")                                                   \
          for (int ks = 0; ks < 4; ks++) {                                    \
            uint4 af[2]; uint2 bf[2];                                         \
            _Pragma("unroll")                                                 \
            for (int i = 0; i < 2; i++) {                                     \
              const float* ap = As_ + (wm*32 + i*16 + g) * TG_STRIDE + ks*8 + tig; \
              af[i].x = f2tf(ap[0]);                                          \
              af[i].y = f2tf(ap[8 * TG_STRIDE]);                              \
              af[i].z = f2tf(ap[4]);                                          \
              af[i].w = f2tf(ap[8 * TG_STRIDE + 4]);                          \
            }                                                                  \
            _Pragma("unroll")                                                 \
            for (int j = 0; j < 2; j++) {                                     \
              const float* bp = Bs_ + (wn*16 + j*8 + g) * TG_STRIDE + ks*8 + tig;  \
              bf[j].x = f2tf(bp[0]);                                          \
              bf[j].y = f2tf(bp[4]);                                          \
            }                                                                  \
            _Pragma("unroll")                                                 \
            for (int i = 0; i < 2; i++)                                       \
                _Pragma("unroll")                                             \
                for (int j = 0; j < 2; j++)                                   \
                    mma8(acc[i][j], af[i], bf[j]);                            \
          } }

    const int nkt = ksz >> 5;
    ISSUE(0);
    ISSUE(1);
    for (int kt = 0; kt < nkt; kt++) {
        if (kt + 2 < nkt) ISSUE(kt + 2);
        const int rem = nkt - 1 - kt;
        if (rem >= 2)      asm volatile("cp.async.wait_group 2;" ::: "memory");
        else if (rem == 1) asm volatile("cp.async.wait_group 1;" ::: "memory");
        else               asm volatile("cp.async.wait_group 0;" ::: "memory");
        __syncthreads();
        TCOMP(kt);
    }
    #undef ISSUE
    #undef TCOMP

    C += (size_t)blockIdx.z * M * N;
    const int mr  = lane >> 2;
    const int nc  = (lane & 3) * 2;
    #pragma unroll
    for (int i = 0; i < 2; i++) {
        #pragma unroll
        for (int j = 0; j < 2; j++) {
            const int mrow = m0 + wm*32 + i*16 + mr;
            const int ncol = n0 + wn*16 + j*8 + nc;
            if (EPI == 4) {
                const float2 bb = *(const float2*)(bias + ncol);
                const float2 cc = *(const float2*)(Cadd + ncol);
                #pragma unroll
                for (int q = 0; q < 2; q++) {
                    const int mm = mrow + q * 8;
                    if (mm < M) {
                        const int r    = (mm < RTOT) ? mm : mm - RTOT;
                        const int coff = (mm < RTOT) ? 0 : DD;
                        float2 v;
                        v.x = tanhf(acc[i][j][q*2+0] + bb.x + cc.x);
                        v.y = tanhf(acc[i][j][q*2+1] + bb.y + cc.y);
                        *(float2*)(g_cat + (size_t)r * DMM + coff + ncol) = v;
                    }
                }
                continue;
            }
            float2 bv = make_float2(0.f, 0.f);
            if (EPI != 3) bv = *(const float2*)(bias + ncol);
            float2 v0 = make_float2(acc[i][j][0] + bv.x, acc[i][j][1] + bv.y);
            float2 v1 = make_float2(acc[i][j][2] + bv.x, acc[i][j][3] + bv.y);
            if (EPI == 5) {
                if (mrow < M)     *(float2*)(C + (size_t)mrow * N + ncol) = v0;
                if (mrow + 8 < M) *(float2*)(C + (size_t)(mrow + 8) * N + ncol) = v1;
                const float rx0 = __shfl_xor_sync(0xffffffffu, v0.x, 1);
                const float ry0 = __shfl_xor_sync(0xffffffffu, v0.y, 1);
                const float rx1 = __shfl_xor_sync(0xffffffffu, v1.x, 1);
                const float ry1 = __shfl_xor_sync(0xffffffffu, v1.y, 1);
                (void)ry1;
                const int jj = ncol >> 2;
                int myrow; float gi, gg, go;
                if ((lane & 1) == 0) { myrow = mrow;     gi = v0.x; gg = rx0;  go = ry0;  }
                else                 { myrow = mrow + 8; gi = rx1;  gg = v1.x; go = v1.y; }
                if (myrow < M) {
                    const float c0 = sigf(gi) * tanhf(gg);
                    const float h  = Cadd[(size_t)myrow * DMM + jj] + sigf(go) * tanhf(c0);
                    g_c0[(size_t)myrow * DMM + jj] = c0;
                    g_hr[(size_t)myrow * DMM + jj] = h;
                }
                continue;
            }
            if (EPI == 1) {
                v0.x = fmaxf(v0.x, 0.f); v0.y = fmaxf(v0.y, 0.f);
                v1.x = fmaxf(v1.x, 0.f); v1.y = fmaxf(v1.y, 0.f);
            }
            if (EPI == 2) {
                if (mrow < M) {
                    float2 c0 = *(const float2*)(Cadd + (size_t)mrow * N + ncol);
                    v0.x += c0.x; v0.y += c0.y;
                }
                if (mrow + 8 < M) {
                    float2 c1 = *(const float2*)(Cadd + (size_t)(mrow + 8) * N + ncol);
                    v1.x += c1.x; v1.y += c1.y;
                }
            }
            if (mrow < M)     *(float2*)(C + (size_t)mrow * N + ncol) = v0;
            if (mrow + 8 < M) *(float2*)(C + (size_t)(mrow + 8) * N + ncol) = v1;
        }
    }
}

// ---------------- residual + layernorm (sums the 2 split-K planes + b2) ----------------
__global__ __launch_bounds__(256)
void ln_kernel(const float* __restrict__ g, const float* __restrict__ b,
               const float* __restrict__ b2)
{
    const int row = blockIdx.x;
    const int t = threadIdx.x;
    const int lane = t & 31, w = t >> 5;
    const float x = g_cat[(size_t)row * DMM + t];
    const float y = g_h2[(size_t)row * DMM + t]
                  + g_h2[(size_t)(RTOT + row) * DMM + t]
                  + b2[t] + x;

    __shared__ float s1[8], s2[8];
    __shared__ float s_mu, s_rs;
    float s = y, ss = y * y;
    #pragma unroll
    for (int o = 16; o; o >>= 1) {
        s  += __shfl_down_sync(0xffffffffu, s,  o);
        ss += __shfl_down_sync(0xffffffffu, ss, o);
    }
    if (lane == 0) { s1[w] = s; s2[w] = ss; }
    __syncthreads();
    if (t == 0) {
        float S = 0.f, SS = 0.f;
        #pragma unroll
        for (int i = 0; i < 8; i++) { S += s1[i]; SS += s2[i]; }
        const float mu = S / DMM;
        const float var = SS / DMM - mu * mu;
        s_mu = mu; s_rs = rsqrtf(var + 1e-5f);
    }
    __syncthreads();
    const float o = g[t] * (y - s_mu) * s_rs + b[t];
    if (row < NQ) g_qg[(size_t)row * DMM + t] = o;
    else          g_sse[(size_t)(row - NQ) * DMM + t] = o;
}

// ---------------- LSTM step 1 + l2norm + final dot (interleaved gates) ----------------
__global__ __launch_bounds__(256)
void final_kernel(float* __restrict__ out)
{
    const int row = blockIdx.x;
    const int t = threadIdx.x;
    const int lane = t & 31, w = t >> 5;
    const float4 g4 = *(const float4*)(g_gates + (size_t)row * GC + t * 4);
    const float ig = sigf(g4.x);
    const float fg = sigf(g4.y);
    const float gg = tanhf(g4.z);
    const float og = sigf(g4.w);
    const float c  = fg * g_c0[(size_t)row * DMM + t] + ig * gg;
    const float h  = g_qg[(size_t)row * DMM + t] + og * tanhf(c);

    float d = h * g_sgn[t];
    float n2 = h * h;
    __shared__ float sd[8], sn[8];
    #pragma unroll
    for (int o = 16; o; o >>= 1) {
        d  += __shfl_down_sync(0xffffffffu, d,  o);
        n2 += __shfl_down_sync(0xffffffffu, n2, o);
    }
    if (lane == 0) { sd[w] = d; sn[w] = n2; }
    __syncthreads();
    if (t == 0) {
        float DT = 0.f, NT = 0.f;
        #pragma unroll
        for (int i = 0; i < 8; i++) { DT += sd[i]; NT += sn[i]; }
        out[row] = DT / fmaxf(sqrtf(NT), 1e-12f);
    }
}

// ---------------- launch ----------------
extern "C" void kernel_launch(void* const* d_in, const int* in_sizes, int n_in,
                              void* d_out, int out_size)
{
    const int*   query   = (const int*)  d_in[0];
    const int*   support = (const int*)  d_in[1];
    const int*   qlc     = (const int*)  d_in[2];
    const int*   qrc     = (const int*)  d_in[4];
    const int*   slc     = (const int*)  d_in[6];
    const int*   src     = (const int*)  d_in[8];
    const float* emb     = (const float*)d_in[10];
    const float* gcnW    = (const float*)d_in[11];
    const float* gbias   = (const float*)d_in[12];
    const float* gb      = (const float*)d_in[13];
    const float* w1      = (const float*)d_in[14];
    const float* b1      = (const float*)d_in[15];
    const float* w2      = (const float*)d_in[16];
    const float* b2      = (const float*)d_in[17];
    const float* lng     = (const float*)d_in[18];
    const float* lnb     = (const float*)d_in[19];
    const float* Wih     = (const float*)d_in[20];
    const float* Whh     = (const float*)d_in[21];
    const float* bih     = (const float*)d_in[22];
    const float* bhh     = (const float*)d_in[23];
    float* out = (float*)d_out;

    float *p_mcat, *p_cat, *p_h1, *p_h2, *p_qg, *p_WihC, *p_WhhC, *p_bsumC, *p_svec;
    float *p_GxC, *p_gates, *p_hr;
    cudaGetSymbolAddress((void**)&p_mcat,  g_mcat);
    cudaGetSymbolAddress((void**)&p_cat,   g_cat);
    cudaGetSymbolAddress((void**)&p_h1,    g_h1);
    cudaGetSymbolAddress((void**)&p_h2,    g_h2);
    cudaGetSymbolAddress((void**)&p_qg,    g_qg);
    cudaGetSymbolAddress((void**)&p_WihC,  g_WihC);
    cudaGetSymbolAddress((void**)&p_WhhC,  g_WhhC);
    cudaGetSymbolAddress((void**)&p_bsumC, g_bsumC);
    cudaGetSymbolAddress((void**)&p_svec,  g_svec);
    cudaGetSymbolAddress((void**)&p_GxC,   g_GxC);
    cudaGetSymbolAddress((void**)&p_gates, g_gates);
    cudaGetSymbolAddress((void**)&p_hr,    g_hr);

    cudaFuncSetAttribute(tgemm<0>, cudaFuncAttributeMaxDynamicSharedMemorySize, TG_SMEM);
    cudaFuncSetAttribute(tgemm<1>, cudaFuncAttributeMaxDynamicSharedMemorySize, TG_SMEM);
    cudaFuncSetAttribute(tgemm<2>, cudaFuncAttributeMaxDynamicSharedMemorySize, TG_SMEM);
    cudaFuncSetAttribute(tgemm<3>, cudaFuncAttributeMaxDynamicSharedMemorySize, TG_SMEM);
    cudaFuncSetAttribute(tgemm<4>, cudaFuncAttributeMaxDynamicSharedMemorySize, TG_SMEM);
    cudaFuncSetAttribute(tgemm<5>, cudaFuncAttributeMaxDynamicSharedMemorySize, TG_SMEM);

    compact_kernel<<<GC * DMM / 256, 256>>>(Wih, Whh, bih, bhh);
    neighbor_all<<<NBLK, 256>>>(emb, qlc, qrc, slc, src, query, support);

    // gcn projection: g_cat = tanh(mcat @ gcnW^T + gbias + gb), scattered layout
    tgemm<4><<<dim3(DD / 64, (NBLK + 63) / 64), 256, TG_SMEM>>>(p_mcat, gcnW, nullptr, NBLK, DD, DMM, gbias, gb);

    // support encoder (batched query + support rows)
    tgemm<1><<<dim3(DFF / 64, (RTOT + 63) / 64), 256, TG_SMEM>>>(p_cat, w1, p_h1, RTOT, DFF, DMM, b1, nullptr);
    tgemm<3><<<dim3(DMM / 64, (RTOT + 63) / 64, 2), 256, TG_SMEM>>>(p_h1, w2, p_h2, RTOT, DMM, DFF, nullptr, nullptr);
    ln_kernel<<<RTOT, 256>>>(lng, lnb, b2);
    svec_kernel<<<GC / 8, 256>>>(Whh);

    // query encoder: Gx GEMM with fused LSTM step-0 (EPI 5, Cadd = qg)
    tgemm<5><<<dim3(GC / 64, NQ / 64), 256, TG_SMEM>>>(p_qg, p_WihC, p_GxC, NQ, GC, DMM, p_bsumC, p_qg);
    tgemm<2><<<dim3(GC / 64, NQ / 64), 256, TG_SMEM>>>(p_hr, p_WhhC, p_gates, NQ, GC, DMM, p_svec, p_GxC);
    final_kernel<<<NQ, 256>>>(out);
}

// round 15
// speedup vs baseline: 1.3009x; 1.0119x over previous
#include <cuda_runtime.h>
#include <math.h>
#include <stdint.h>

#define NQ    1024
#define FEWS  5
#define MCAND 200
#define KSEL  32
#define DD    128
#define DMM   256
#define DFF   512
#define HHH   512
#define GC    1024            // compacted gate columns, interleaved (j*4 + gate)
#define RTOT  (NQ + FEWS)     // 1029
#define NBLK  (2*NQ + 2*FEWS) // 2058 neighbor tasks

#define TG_STRIDE 36                      // floats per smem row (conflict-free, 16B-mult)
#define TG_TILEF  (64 * TG_STRIDE)        // floats per operand stage
#define TG_SMEM   (4 * 2 * TG_TILEF * 4)  // 4 stages x (A,B) x bytes = 73728

// ---------------- workspace (device globals; no allocations) ----------------
__device__ float g_mcat [NBLK * DMM];
__device__ float g_cat  [RTOT * DMM];
__device__ float g_h1   [RTOT * DFF];
__device__ float g_h2   [2 * RTOT * DMM];   // split-K planes / gcn planes (reused)
__device__ float g_qg   [NQ   * DMM];
__device__ float g_sse  [FEWS * DMM];
__device__ float g_sgn  [DMM];
__device__ float g_WihC [GC * DMM];
__device__ float g_WhhC [GC * DMM];
__device__ float g_bsumC[GC];
__device__ float g_svec [GC];
__device__ float g_GxC  [NQ * GC];
__device__ float g_c0   [NQ * DMM];
__device__ float g_hr   [NQ * DMM];
__device__ float g_dots [NQ];
__device__ float g_nrm  [NQ];

__device__ __forceinline__ int orig_col(int r) { return (r & 3) * 512 + (r >> 2); }
__device__ __forceinline__ float sigf(float x) { return 1.f / (1.f + expf(-x)); }

__device__ __forceinline__ uint32_t f2tf(float x) {
    uint32_t r;
    asm("cvt.rna.tf32.f32 %0, %1;" : "=r"(r) : "f"(x));
    return r;
}

__device__ __forceinline__ void mma8(float* c, const uint4& a, const uint2& b) {
    asm volatile(
        "mma.sync.aligned.m16n8k8.row.col.f32.tf32.tf32.f32 "
        "{%0,%1,%2,%3}, {%4,%5,%6,%7}, {%8,%9}, {%0,%1,%2,%3};"
        : "+f"(c[0]), "+f"(c[1]), "+f"(c[2]), "+f"(c[3])
        : "r"(a.x), "r"(a.y), "r"(a.z), "r"(a.w), "r"(b.x), "r"(b.y));
}

// ---------------- weight compaction + per-launch accumulator zeroing ----------------
__global__ __launch_bounds__(256)
void compact_kernel(const float* __restrict__ Wih, const float* __restrict__ Whh,
                    const float* __restrict__ bih, const float* __restrict__ bhh)
{
    const int idx = blockIdx.x * 256 + threadIdx.x;
    const int r = idx >> 8, c = idx & 255;
    const int o = orig_col(r);
    g_WihC[idx] = Wih[(size_t)o * DMM + c];
    g_WhhC[idx] = Whh[(size_t)o * HHH + c];
    if (c == 0) g_bsumC[r] = bih[o] + bhh[o];
    if (idx < NQ) { g_dots[idx] = 0.f; g_nrm[idx] = 0.f; }
}

// ---------------- svec + support mean + sgn (merged) ----------------
__global__ __launch_bounds__(256)
void svec_kernel(const float* __restrict__ Whh)
{
    const int t = threadIdx.x;
    const int lane = t & 31, w = t >> 5;
    __shared__ float ssg[DMM];
    __shared__ float s1[8];
    __shared__ float s_n;

    float s = 0.f;
    #pragma unroll
    for (int r = 0; r < FEWS; r++) s += g_sse[r * DMM + t];
    ssg[t] = s * (1.f / FEWS);
    __syncthreads();

    const int r = blockIdx.x * 8 + w;
    const int o = orig_col(r);
    const float* wr = Whh + (size_t)o * HHH + DMM;
    float p = 0.f;
    #pragma unroll
    for (int c = lane; c < DMM; c += 32) p += wr[c] * ssg[c];
    #pragma unroll
    for (int off = 16; off; off >>= 1) p += __shfl_down_sync(0xffffffffu, p, off);
    if (lane == 0) g_svec[r] = p;

    if (blockIdx.x == 0) {
        __syncthreads();
        float q = ssg[t] * ssg[t];
        #pragma unroll
        for (int off = 16; off; off >>= 1) q += __shfl_down_sync(0xffffffffu, q, off);
        if (lane == 0) s1[w] = q;
        __syncthreads();
        if (t == 0) {
            float S = 0.f;
            #pragma unroll
            for (int i = 0; i < 8; i++) S += s1[i];
            s_n = fmaxf(sqrtf(S), 1e-12f);
        }
        __syncthreads();
        g_sgn[t] = ssg[t] / s_n;
    }
}

// ---------------- neighbor encoder: sims + top-K + mean only ----------------
__global__ __launch_bounds__(256)
void neighbor_all(const float* __restrict__ emb,
                  const int* __restrict__ qlc, const int* __restrict__ qrc,
                  const int* __restrict__ slc, const int* __restrict__ src,
                  const int* __restrict__ query, const int* __restrict__ support)
{
    const int b = blockIdx.x;
    const int t = threadIdx.x;
    const int lane = t & 31;
    const int w = t >> 5;

    const int* conn_row;
    int cid, tt;
    if (b < NQ)            { conn_row = qlc + (size_t)b * MCAND * 2;                 cid = query[b * 2 + 0];   tt = b; }
    else if (b < 2 * NQ)   { int rb = b - NQ;        conn_row = qrc + (size_t)rb * MCAND * 2; cid = query[rb * 2 + 1];   tt = RTOT + rb; }
    else if (b < 2*NQ+FEWS){ int rb = b - 2*NQ;      conn_row = slc + (size_t)rb * MCAND * 2; cid = support[rb*2 + 0];   tt = NQ + rb; }
    else                   { int rb = b - 2*NQ-FEWS; conn_row = src + (size_t)rb * MCAND * 2; cid = support[rb*2 + 1];   tt = RTOT + NQ + rb; }

    __shared__ __align__(16) float s_center[DD];
    __shared__ float s_sim [MCAND];
    __shared__ int   s_ridx[MCAND];
    __shared__ int   s_eidx[MCAND];
    __shared__ int   s_selr[KSEL];
    __shared__ int   s_sele[KSEL];
    __shared__ float s_red[8];
    __shared__ float s_cn;

    for (int n = t; n < MCAND; n += 256) {
        s_ridx[n] = conn_row[n * 2 + 0];
        s_eidx[n] = conn_row[n * 2 + 1];
    }
    float cv = 0.f;
    if (t < DD) { cv = emb[(size_t)cid * DD + t]; s_center[t] = cv; }

    float p = cv * cv;
    #pragma unroll
    for (int o = 16; o; o >>= 1) p += __shfl_down_sync(0xffffffffu, p, o);
    if (lane == 0) s_red[w] = p;
    __syncthreads();
    if (t == 0) {
        float s = 0.f;
        #pragma unroll
        for (int i = 0; i < 8; i++) s += s_red[i];
        s_cn = sqrtf(s);
    }
    __syncthreads();
    const float cn = s_cn;

    const float4 z4 = make_float4(0.f, 0.f, 0.f, 0.f);
    const float4 c4 = *(const float4*)(s_center + lane * 4);
    for (int nb = w; nb < MCAND; nb += 32) {
        int   ni[4];
        bool  va[4];
        float4 e[4];
        #pragma unroll
        for (int q = 0; q < 4; q++) {
            ni[q] = nb + q * 8;
            va[q] = ni[q] < MCAND;
            e[q]  = va[q] ? *(const float4*)(emb + (size_t)s_eidx[ni[q]] * DD + lane * 4) : z4;
        }
        float num[4], nrm[4];
        #pragma unroll
        for (int q = 0; q < 4; q++) {
            num[q] = e[q].x*c4.x + e[q].y*c4.y + e[q].z*c4.z + e[q].w*c4.w;
            nrm[q] = e[q].x*e[q].x + e[q].y*e[q].y + e[q].z*e[q].z + e[q].w*e[q].w;
        }
        #pragma unroll
        for (int o = 16; o; o >>= 1) {
            #pragma unroll
            for (int q = 0; q < 4; q++) {
                num[q] += __shfl_down_sync(0xffffffffu, num[q], o);
                nrm[q] += __shfl_down_sync(0xffffffffu, nrm[q], o);
            }
        }
        if (lane == 0) {
            #pragma unroll
            for (int q = 0; q < 4; q++)
                if (va[q]) s_sim[ni[q]] = num[q] / fmaxf(cn * sqrtf(nrm[q]), 1e-8f);
        }
    }
    __syncthreads();

    // top-K with jax.lax.top_k tie-break (lower index wins); rank is a permutation
    if (t < MCAND) {
        const float v = s_sim[t];
        int r = 0;
        for (int i = 0; i < MCAND; i++) {
            const float u = s_sim[i];
            r += (u > v) || (u == v && i < t);
        }
        if (r < KSEL) { s_selr[r] = s_ridx[t]; s_sele[r] = s_eidx[t]; }
    }
    __syncthreads();

    {
        float acc = 0.f;
        if (t < DD) {
            #pragma unroll 8
            for (int k = 0; k < KSEL; k++) acc += emb[(size_t)s_selr[k] * DD + t];
        } else {
            const int d = t - DD;
            #pragma unroll 8
            for (int k = 0; k < KSEL; k++) acc += emb[(size_t)s_sele[k] * DD + d];
        }
        g_mcat[(size_t)tt * DMM + t] = acc * (1.f / KSEL);
    }
}

// ---------------- gcn combine: sum 2 split-K planes + biases, tanh, scatter ----------------
__global__ __launch_bounds__(256)
void gcn_combine(const float* __restrict__ gbias, const float* __restrict__ gb)
{
    const int idx = blockIdx.x * 256 + threadIdx.x;   // NBLK * DD
    const int mm = idx >> 7;
    const int c  = idx & 127;
    const float v = g_h2[idx] + g_h2[idx + NBLK * DD] + gbias[c] + gb[c];
    const int r    = (mm < RTOT) ? mm : mm - RTOT;
    const int coff = (mm < RTOT) ? 0 : DD;
    g_cat[(size_t)r * DMM + coff + c] = tanhf(v);
}

// ---------------- tf32 tensor-core GEMM (cp.async pipeline) ----------------
// C[M,N] = A[M,K] @ B[N,K]^T. Block tile 64x64, BK=32, 8 warps (2m x 4n).
// 4-stage smem ring filled by cp.async.cg (16B), prefetch distance 2,
// wait_group + 1 barrier per ktile. Row-major smem, stride 36 (conflict-free).
// Fragments converted with cvt.rna.tf32 after LDS.
// EPI: 1 = relu(+bias[n]), 3 = raw (split-K plane),
//      5 = +bias[n], store C, fused LSTM step-0 (c0/hr; Cadd = qg),
//      6 = +bias[n]+Cadd, fused LSTM step-1 + h + atomic dot/norm partials (no C store)
template <int EPI>
__global__ __launch_bounds__(256)
void tgemm(const float* __restrict__ A, const float* __restrict__ Bm,
           float* __restrict__ C, int M, int N, int K,
           const float* __restrict__ bias, const float* __restrict__ Cadd)
{
    extern __shared__ float smx[];
    const uint32_t smbase = (uint32_t)__cvta_generic_to_shared(smx);

    const int t    = threadIdx.x;
    const int lane = t & 31;
    const int w    = t >> 5;
    const int wm   = w >> 2;
    const int wn   = w & 3;
    const int g    = lane >> 2;
    const int tig  = lane & 3;
    const int m0   = blockIdx.y * 64;
    const int n0   = blockIdx.x * 64;
    const int ksz  = K / gridDim.z;
    const int kb   = blockIdx.z * ksz;

    float acc[2][2][4];
    #pragma unroll
    for (int i = 0; i < 2; i++)
        #pragma unroll
        for (int j = 0; j < 2; j++)
            #pragma unroll
            for (int q = 0; q < 4; q++) acc[i][j][q] = 0.f;

    #define ISSUE(kt)                                                         \
        { const int stg = (kt) & 3;                                           \
          const uint32_t sA = smbase + (uint32_t)(stg * 2 * TG_TILEF) * 4u;   \
          const uint32_t sB = sA + (uint32_t)TG_TILEF * 4u;                   \
          _Pragma("unroll")                                                   \
          for (int p = 0; p < 2; p++) {                                       \
            const int c   = t + p * 256;                                      \
            const int row = c >> 3;                                           \
            const int ch  = (c & 7) * 4;                                      \
            const int m   = m0 + row;                                         \
            const int mc  = (m < M) ? m : (M - 1);                            \
            const int szA = (m < M) ? 16 : 0;                                 \
            const float* srcA = A + (size_t)mc * K + kb + (kt) * 32 + ch;     \
            const uint32_t dA = sA + (uint32_t)(row * TG_STRIDE + ch) * 4u;   \
            asm volatile("cp.async.cg.shared.global [%0], [%1], 16, %2;"      \
                         :: "r"(dA), "l"(srcA), "r"(szA));                    \
            const float* srcB = Bm + (size_t)(n0 + row) * K + kb + (kt)*32 + ch; \
            const uint32_t dB = sB + (uint32_t)(row * TG_STRIDE + ch) * 4u;   \
            asm volatile("cp.async.cg.shared.global [%0], [%1], 16;"          \
                         :: "r"(dB), "l"(srcB));                              \
          }                                                                    \
          asm volatile("cp.async.commit_group;" ::: "memory"); }

    #define TCOMP(kt)                                                         \
        { const int stg = (kt) & 3;                                           \
          const float* As_ = smx + stg * 2 * TG_TILEF;                        \
          const float* Bs_ = As_ + TG_TILEF;                                  \
          _Pragma("unroll")                                                   \
          for (int ks = 0; ks < 4; ks++) {                                    \
            uint4 af[2]; uint2 bf[2];                                         \
            _Pragma("unroll")                                                 \
            for (int i = 0; i < 2; i++) {                                     \
              const float* ap = As_ + (wm*32 + i*16 + g) * TG_STRIDE + ks*8 + tig; \
              af[i].x = f2tf(ap[0]);                                          \
              af[i].y = f2tf(ap[8 * TG_STRIDE]);                              \
              af[i].z = f2tf(ap[4]);                                          \
              af[i].w = f2tf(ap[8 * TG_STRIDE + 4]);                          \
            }                                                                  \
            _Pragma("unroll")                                                 \
            for (int j = 0; j < 2; j++) {                                     \
              const float* bp = Bs_ + (wn*16 + j*8 + g) * TG_STRIDE + ks*8 + tig;  \
              bf[j].x = f2tf(bp[0]);                                          \
              bf[j].y = f2tf(bp[4]);                                          \
            }                                                                  \
            _Pragma("unroll")                                                 \
            for (int i = 0; i < 2; i++)                                       \
                _Pragma("unroll")                                             \
                for (int j = 0; j < 2; j++)                                   \
                    mma8(acc[i][j], af[i], bf[j]);                            \
          } }

    const int nkt = ksz >> 5;
    ISSUE(0);
    ISSUE(1);
    for (int kt = 0; kt < nkt; kt++) {
        if (kt + 2 < nkt) ISSUE(kt + 2);
        const int rem = nkt - 1 - kt;
        if (rem >= 2)      asm volatile("cp.async.wait_group 2;" ::: "memory");
        else if (rem == 1) asm volatile("cp.async.wait_group 1;" ::: "memory");
        else               asm volatile("cp.async.wait_group 0;" ::: "memory");
        __syncthreads();
        TCOMP(kt);
    }
    #undef ISSUE
    #undef TCOMP

    C += (size_t)blockIdx.z * M * N;
    const int mr  = lane >> 2;
    const int nc  = (lane & 3) * 2;
    float dacc = 0.f, nacc = 0.f;
    #pragma unroll
    for (int i = 0; i < 2; i++) {
        #pragma unroll
        for (int j = 0; j < 2; j++) {
            const int mrow = m0 + wm*32 + i*16 + mr;
            const int ncol = n0 + wn*16 + j*8 + nc;
            float2 bv = make_float2(0.f, 0.f);
            if (EPI != 3) bv = *(const float2*)(bias + ncol);
            float2 v0 = make_float2(acc[i][j][0] + bv.x, acc[i][j][1] + bv.y);
            float2 v1 = make_float2(acc[i][j][2] + bv.x, acc[i][j][3] + bv.y);
            if (EPI == 5) {
                if (mrow < M)     *(float2*)(C + (size_t)mrow * N + ncol) = v0;
                if (mrow + 8 < M) *(float2*)(C + (size_t)(mrow + 8) * N + ncol) = v1;
                const float rx0 = __shfl_xor_sync(0xffffffffu, v0.x, 1);
                const float ry0 = __shfl_xor_sync(0xffffffffu, v0.y, 1);
                const float rx1 = __shfl_xor_sync(0xffffffffu, v1.x, 1);
                const float ry1 = __shfl_xor_sync(0xffffffffu, v1.y, 1);
                (void)ry1;
                const int jj = ncol >> 2;
                int myrow; float gi, gg, go;
                if ((lane & 1) == 0) { myrow = mrow;     gi = v0.x; gg = rx0;  go = ry0;  }
                else                 { myrow = mrow + 8; gi = rx1;  gg = v1.x; go = v1.y; }
                if (myrow < M) {
                    const float c0 = sigf(gi) * tanhf(gg);
                    const float h  = Cadd[(size_t)myrow * DMM + jj] + sigf(go) * tanhf(c0);
                    g_c0[(size_t)myrow * DMM + jj] = c0;
                    g_hr[(size_t)myrow * DMM + jj] = h;
                }
                continue;
            }
            if (EPI == 6) {
                // add Gx (Cadd) then fused LSTM step-1 + h + partial reductions
                {
                    const float2 c0r = *(const float2*)(Cadd + (size_t)mrow * N + ncol);
                    v0.x += c0r.x; v0.y += c0r.y;
                    const float2 c1r = *(const float2*)(Cadd + (size_t)(mrow + 8) * N + ncol);
                    v1.x += c1r.x; v1.y += c1r.y;
                }
                const float rx0 = __shfl_xor_sync(0xffffffffu, v0.x, 1);
                const float ry0 = __shfl_xor_sync(0xffffffffu, v0.y, 1);
                const float rx1 = __shfl_xor_sync(0xffffffffu, v1.x, 1);
                const float ry1 = __shfl_xor_sync(0xffffffffu, v1.y, 1);
                const int jj = ncol >> 2;
                int myrow; float gi, gf, gg, go;
                if ((lane & 1) == 0) { myrow = mrow;     gi = v0.x; gf = v0.y; gg = rx0;  go = ry0;  }
                else                 { myrow = mrow + 8; gi = rx1;  gf = ry1;  gg = v1.x; go = v1.y; }
                const float cc = sigf(gf) * g_c0[(size_t)myrow * DMM + jj]
                               + sigf(gi) * tanhf(gg);
                const float h  = g_qg[(size_t)myrow * DMM + jj] + sigf(go) * tanhf(cc);
                if (j == 0) { dacc = 0.f; nacc = 0.f; }
                dacc += h * g_sgn[jj];
                nacc += h * h;
                if (j == 1) {
                    atomicAdd(&g_dots[myrow], dacc);
                    atomicAdd(&g_nrm[myrow],  nacc);
                }
                continue;
            }
            if (EPI == 1) {
                v0.x = fmaxf(v0.x, 0.f); v0.y = fmaxf(v0.y, 0.f);
                v1.x = fmaxf(v1.x, 0.f); v1.y = fmaxf(v1.y, 0.f);
            }
            if (mrow < M)     *(float2*)(C + (size_t)mrow * N + ncol) = v0;
            if (mrow + 8 < M) *(float2*)(C + (size_t)(mrow + 8) * N + ncol) = v1;
        }
    }
}

// ---------------- residual + layernorm (sums the 2 split-K planes + b2) ----------------
__global__ __launch_bounds__(256)
void ln_kernel(const float* __restrict__ g, const float* __restrict__ b,
               const float* __restrict__ b2)
{
    const int row = blockIdx.x;
    const int t = threadIdx.x;
    const int lane = t & 31, w = t >> 5;
    const float x = g_cat[(size_t)row * DMM + t];
    const float y = g_h2[(size_t)row * DMM + t]
                  + g_h2[(size_t)(RTOT + row) * DMM + t]
                  + b2[t] + x;

    __shared__ float s1[8], s2[8];
    __shared__ float s_mu, s_rs;
    float s = y, ss = y * y;
    #pragma unroll
    for (int o = 16; o; o >>= 1) {
        s  += __shfl_down_sync(0xffffffffu, s,  o);
        ss += __shfl_down_sync(0xffffffffu, ss, o);
    }
    if (lane == 0) { s1[w] = s; s2[w] = ss; }
    __syncthreads();
    if (t == 0) {
        float S = 0.f, SS = 0.f;
        #pragma unroll
        for (int i = 0; i < 8; i++) { S += s1[i]; SS += s2[i]; }
        const float mu = S / DMM;
        const float var = SS / DMM - mu * mu;
        s_mu = mu; s_rs = rsqrtf(var + 1e-5f);
    }
    __syncthreads();
    const float o = g[t] * (y - s_mu) * s_rs + b[t];
    if (row < NQ) g_qg[(size_t)row * DMM + t] = o;
    else          g_sse[(size_t)(row - NQ) * DMM + t] = o;
}

// ---------------- finalize: out = dot / max(norm, eps) ----------------
__global__ __launch_bounds__(256)
void finalize_kernel(float* __restrict__ out)
{
    const int i = blockIdx.x * 256 + threadIdx.x;
    if (i < NQ) out[i] = g_dots[i] / fmaxf(sqrtf(g_nrm[i]), 1e-12f);
}

// ---------------- launch ----------------
extern "C" void kernel_launch(void* const* d_in, const int* in_sizes, int n_in,
                              void* d_out, int out_size)
{
    const int*   query   = (const int*)  d_in[0];
    const int*   support = (const int*)  d_in[1];
    const int*   qlc     = (const int*)  d_in[2];
    const int*   qrc     = (const int*)  d_in[4];
    const int*   slc     = (const int*)  d_in[6];
    const int*   src     = (const int*)  d_in[8];
    const float* emb     = (const float*)d_in[10];
    const float* gcnW    = (const float*)d_in[11];
    const float* gbias   = (const float*)d_in[12];
    const float* gb      = (const float*)d_in[13];
    const float* w1      = (const float*)d_in[14];
    const float* b1      = (const float*)d_in[15];
    const float* w2      = (const float*)d_in[16];
    const float* b2      = (const float*)d_in[17];
    const float* lng     = (const float*)d_in[18];
    const float* lnb     = (const float*)d_in[19];
    const float* Wih     = (const float*)d_in[20];
    const float* Whh     = (const float*)d_in[21];
    const float* bih     = (const float*)d_in[22];
    const float* bhh     = (const float*)d_in[23];
    float* out = (float*)d_out;

    float *p_mcat, *p_cat, *p_h1, *p_h2, *p_qg, *p_WihC, *p_WhhC, *p_bsumC, *p_svec;
    float *p_GxC, *p_hr;
    cudaGetSymbolAddress((void**)&p_mcat,  g_mcat);
    cudaGetSymbolAddress((void**)&p_cat,   g_cat);
    cudaGetSymbolAddress((void**)&p_h1,    g_h1);
    cudaGetSymbolAddress((void**)&p_h2,    g_h2);
    cudaGetSymbolAddress((void**)&p_qg,    g_qg);
    cudaGetSymbolAddress((void**)&p_WihC,  g_WihC);
    cudaGetSymbolAddress((void**)&p_WhhC,  g_WhhC);
    cudaGetSymbolAddress((void**)&p_bsumC, g_bsumC);
    cudaGetSymbolAddress((void**)&p_svec,  g_svec);
    cudaGetSymbolAddress((void**)&p_GxC,   g_GxC);
    cudaGetSymbolAddress((void**)&p_hr,    g_hr);

    cudaFuncSetAttribute(tgemm<1>, cudaFuncAttributeMaxDynamicSharedMemorySize, TG_SMEM);
    cudaFuncSetAttribute(tgemm<3>, cudaFuncAttributeMaxDynamicSharedMemorySize, TG_SMEM);
    cudaFuncSetAttribute(tgemm<5>, cudaFuncAttributeMaxDynamicSharedMemorySize, TG_SMEM);
    cudaFuncSetAttribute(tgemm<6>, cudaFuncAttributeMaxDynamicSharedMemorySize, TG_SMEM);

    compact_kernel<<<GC * DMM / 256, 256>>>(Wih, Whh, bih, bhh);
    neighbor_all<<<NBLK, 256>>>(emb, qlc, qrc, slc, src, query, support);

    // gcn projection via raw split-K (z=2, 132 blocks) into g_h2 planes, then combine
    tgemm<3><<<dim3(DD / 64, (NBLK + 63) / 64, 2), 256, TG_SMEM>>>(p_mcat, gcnW, p_h2, NBLK, DD, DMM, nullptr, nullptr);
    gcn_combine<<<NBLK * DD / 256, 256>>>(gbias, gb);

    // support encoder (batched query + support rows)
    tgemm<1><<<dim3(DFF / 64, (RTOT + 63) / 64), 256, TG_SMEM>>>(p_cat, w1, p_h1, RTOT, DFF, DMM, b1, nullptr);
    tgemm<3><<<dim3(DMM / 64, (RTOT + 63) / 64, 2), 256, TG_SMEM>>>(p_h1, w2, p_h2, RTOT, DMM, DFF, nullptr, nullptr);
    ln_kernel<<<RTOT, 256>>>(lng, lnb, b2);
    svec_kernel<<<GC / 8, 256>>>(Whh);

    // query encoder: Gx GEMM with fused LSTM step-0, then gates GEMM with fused
    // step-1 + final dot/norm partial reduction (atomics)
    tgemm<5><<<dim3(GC / 64, NQ / 64), 256, TG_SMEM>>>(p_qg, p_WihC, p_GxC, NQ, GC, DMM, p_bsumC, p_qg);
    tgemm<6><<<dim3(GC / 64, NQ / 64), 256, TG_SMEM>>>(p_hr, p_WhhC, p_GxC, NQ, GC, DMM, p_svec, p_GxC);
    finalize_kernel<<<NQ / 256, 256>>>(out);
}